// round 7
// baseline (speedup 1.0000x reference)
#include <cuda_runtime.h>
#include <cuda_bf16.h>
#include <stdint.h>

#define N_NODES   10000
#define N_EDGES   160000
#define F_IN      512
#define K_TOT     1024
#define H_FEATS   512
#define N_CLASSES 128

// ---------------------------------------------------------------------------
// Device scratch
// ---------------------------------------------------------------------------
__device__ int   g_cnt[N_NODES];
__device__ int   g_cur[N_NODES];
__device__ int   g_off[N_NODES + 1];
__device__ int   g_adj[N_EDGES];
__device__ float g_hN [(size_t)N_NODES * F_IN];       // agg(h)
__device__ float g_h1 [(size_t)N_NODES * H_FEATS];    // relu(layer1)
__device__ float g_Y2 [(size_t)N_NODES * N_CLASSES];  // h1 @ W2_bot
__device__ float g_P2 [(size_t)N_NODES * N_CLASSES];  // h1 @ W2_top + b2
__device__ float g_W1tH[(size_t)H_FEATS   * K_TOT];   // transposed + tf32-hi
__device__ float g_W1tL[(size_t)H_FEATS   * K_TOT];   // residual lo
__device__ float g_W2tH[(size_t)N_CLASSES * K_TOT];
__device__ float g_W2tL[(size_t)N_CLASSES * K_TOT];

// ---------------------------------------------------------------------------
// helpers
// ---------------------------------------------------------------------------
__device__ __forceinline__ void cp_async16(uint32_t dst, const void* src, int src_bytes) {
    asm volatile("cp.async.cg.shared.global [%0], [%1], 16, %2;"
                 :: "r"(dst), "l"(src), "r"(src_bytes));
}
__device__ __forceinline__ void cp_commit() {
    asm volatile("cp.async.commit_group;" ::: "memory");
}
template <int N>
__device__ __forceinline__ void cp_wait() {
    asm volatile("cp.async.wait_group %0;" :: "n"(N) : "memory");
}
__device__ __forceinline__ void mma_tf32(float* c, const uint32_t* a, const uint32_t* b) {
    asm volatile(
        "mma.sync.aligned.m16n8k8.row.col.f32.tf32.tf32.f32 "
        "{%0,%1,%2,%3}, {%4,%5,%6,%7}, {%8,%9}, {%0,%1,%2,%3};"
        : "+f"(c[0]), "+f"(c[1]), "+f"(c[2]), "+f"(c[3])
        : "r"(a[0]), "r"(a[1]), "r"(a[2]), "r"(a[3]), "r"(b[0]), "r"(b[1]));
}
__device__ __forceinline__ uint32_t f32_to_tf32_rna(float x) {
    uint32_t r;
    asm("cvt.rna.tf32.f32 %0, %1;" : "=r"(r) : "f"(x));
    return r;
}
__device__ __forceinline__ void tf32_split(float x, uint32_t& hi, uint32_t& lo) {
    hi = f32_to_tf32_rna(x);
    lo = __float_as_uint(x - __uint_as_float(hi));
}

// ---------------------------------------------------------------------------
// CSR build
// ---------------------------------------------------------------------------
__global__ void count_kernel(const int* __restrict__ dst) {
    int e = blockIdx.x * blockDim.x + threadIdx.x;
    if (e < N_EDGES) atomicAdd(&g_cnt[dst[e]], 1);
}
__global__ void scan_kernel() {
    __shared__ int wsum[32];
    __shared__ int chunk_total;
    const int lane = threadIdx.x & 31;
    const int wid  = threadIdx.x >> 5;
    int running = 0;
    for (int base = 0; base < N_NODES; base += 1024) {
        int i = base + threadIdx.x;
        int v = (i < N_NODES) ? g_cnt[i] : 0;
        int s = v;
        #pragma unroll
        for (int o = 1; o < 32; o <<= 1) {
            int u = __shfl_up_sync(0xffffffffu, s, o);
            if (lane >= o) s += u;
        }
        if (lane == 31) wsum[wid] = s;
        __syncthreads();
        if (wid == 0) {
            int ws = wsum[lane];
            #pragma unroll
            for (int o = 1; o < 32; o <<= 1) {
                int u = __shfl_up_sync(0xffffffffu, ws, o);
                if (lane >= o) ws += u;
            }
            wsum[lane] = ws;
            if (lane == 31) chunk_total = ws;
        }
        __syncthreads();
        int wpref = (wid > 0) ? wsum[wid - 1] : 0;
        if (i < N_NODES) g_off[i] = running + wpref + s - v;
        running += chunk_total;
        __syncthreads();
    }
    if (threadIdx.x == 0) g_off[N_NODES] = running;
}
__global__ void fill_kernel(const int* __restrict__ src, const int* __restrict__ dst) {
    int e = blockIdx.x * blockDim.x + threadIdx.x;
    if (e < N_EDGES) {
        int d = dst[e];
        int p = atomicAdd(&g_cur[d], 1);
        g_adj[g_off[d] + p] = src[e];
    }
}

// ---------------------------------------------------------------------------
// Aggregations
// ---------------------------------------------------------------------------
__global__ void agg512_kernel(const float* __restrict__ H, float* __restrict__ out) {
    int n   = blockIdx.x;
    int st  = g_off[n];
    int deg = g_off[n + 1] - st;
    int c4  = threadIdx.x;
    float4 acc = make_float4(0.f, 0.f, 0.f, 0.f);
    int e = 0;
    for (; e + 1 < deg; e += 2) {
        int s0 = g_adj[st + e];
        int s1 = g_adj[st + e + 1];
        float4 v0 = *(const float4*)(H + (size_t)s0 * 512 + c4 * 4);
        float4 v1 = *(const float4*)(H + (size_t)s1 * 512 + c4 * 4);
        acc.x += v0.x + v1.x; acc.y += v0.y + v1.y;
        acc.z += v0.z + v1.z; acc.w += v0.w + v1.w;
    }
    if (e < deg) {
        int s0 = g_adj[st + e];
        float4 v0 = *(const float4*)(H + (size_t)s0 * 512 + c4 * 4);
        acc.x += v0.x; acc.y += v0.y; acc.z += v0.z; acc.w += v0.w;
    }
    float inv = (deg > 0) ? (1.0f / (float)deg) : 0.0f;
    acc.x *= inv; acc.y *= inv; acc.z *= inv; acc.w *= inv;
    *(float4*)(out + (size_t)n * 512 + c4 * 4) = acc;
}

// out[n] = P[n] + mean_{s in N(n)} Y[s]     (width 128)
__global__ void agg128_final_kernel(const float* __restrict__ Y,
                                    const float* __restrict__ P,
                                    float* __restrict__ out) {
    int n = blockIdx.x * 4 + (threadIdx.x >> 5);
    int lane = threadIdx.x & 31;
    if (n >= N_NODES) return;
    int st  = g_off[n];
    int deg = g_off[n + 1] - st;
    float4 acc = make_float4(0.f, 0.f, 0.f, 0.f);
    int e = 0;
    for (; e + 1 < deg; e += 2) {
        int s0 = g_adj[st + e];
        int s1 = g_adj[st + e + 1];
        float4 v0 = *(const float4*)(Y + (size_t)s0 * 128 + lane * 4);
        float4 v1 = *(const float4*)(Y + (size_t)s1 * 128 + lane * 4);
        acc.x += v0.x + v1.x; acc.y += v0.y + v1.y;
        acc.z += v0.z + v1.z; acc.w += v0.w + v1.w;
    }
    if (e < deg) {
        int s0 = g_adj[st + e];
        float4 v0 = *(const float4*)(Y + (size_t)s0 * 128 + lane * 4);
        acc.x += v0.x; acc.y += v0.y; acc.z += v0.z; acc.w += v0.w;
    }
    float inv = (deg > 0) ? (1.0f / (float)deg) : 0.0f;
    float4 p = *(const float4*)(P + (size_t)n * 128 + lane * 4);
    acc.x = acc.x * inv + p.x; acc.y = acc.y * inv + p.y;
    acc.z = acc.z * inv + p.z; acc.w = acc.w * inv + p.w;
    *(float4*)(out + (size_t)n * 128 + lane * 4) = acc;
}

// ---------------------------------------------------------------------------
// Transpose + tf32 hi/lo split: in[R][C] (k-major W) -> ohi/olo [C][R]
// ---------------------------------------------------------------------------
__global__ void transpose_split_kernel(const float* __restrict__ in,
                                       float* __restrict__ ohi, float* __restrict__ olo,
                                       int R, int C) {
    __shared__ float tile[32][33];
    int c = blockIdx.x * 32 + threadIdx.x;
    int r = blockIdx.y * 32 + threadIdx.y;
    #pragma unroll
    for (int j = 0; j < 32; j += 8)
        if (r + j < R && c < C) tile[threadIdx.y + j][threadIdx.x] = in[(size_t)(r + j) * C + c];
    __syncthreads();
    int c2 = blockIdx.y * 32 + threadIdx.x;   // output col  (k index)
    int r2 = blockIdx.x * 32 + threadIdx.y;   // output row  (n index)
    #pragma unroll
    for (int j = 0; j < 32; j += 8)
        if (r2 + j < C && c2 < R) {
            float x = tile[threadIdx.x][threadIdx.y + j];
            uint32_t hi, lo;
            tf32_split(x, hi, lo);
            ohi[(size_t)(r2 + j) * R + c2] = __uint_as_float(hi);
            olo[(size_t)(r2 + j) * R + c2] = __uint_as_float(lo);
        }
}

// ---------------------------------------------------------------------------
// 3xTF32 GEMM, B pre-split + pre-transposed (n-major, conflict-free):
//   C[M,N] = concatK(A0,A1) @ W[:, koff:koff+K]^T + bias (+ReLU)
// block 128x128, BK=16, 2-stage cp.async, occ 2, dynamic SMEM 60KB.
// SMEM floats: As[2][128][20] | Bhi[2][128][20] | Blo[2][128][20]
// dual mode: gridDim.x==2 selects {C0,koff} / {C1,koffAlt,bias}.
// ---------------------------------------------------------------------------
#define GEMM_SMEM_FLOATS (3 * 2 * 128 * 20)
#define GEMM_SMEM_BYTES  (GEMM_SMEM_FLOATS * 4)

__global__ __launch_bounds__(256, 2)
void gemm_mma_kernel(const float* __restrict__ A0, const float* __restrict__ A1,
                     const float* __restrict__ Whi, const float* __restrict__ Wlo,
                     const float* __restrict__ bias,
                     float* __restrict__ C, float* __restrict__ Calt,
                     int M, int N, int do_relu, int nstages,
                     int koff, int koffAlt, int dual) {
    extern __shared__ float smem[];
    float* AS = smem;                 // [2][128][20]
    float* BH = smem + 5120;          // [2][128][20]
    float* BL = smem + 10240;         // [2][128][20]

    const int t     = threadIdx.x;
    const int lane  = t & 31;
    const int wid   = t >> 5;
    const int warpM = wid & 3;
    const int warpN = wid >> 2;
    const int gid   = lane >> 2;
    const int tig   = lane & 3;
    const int m0    = blockIdx.y * 128;

    int n0 = blockIdx.x * 128;
    const float* biasp = bias;
    if (dual) {
        n0 = 0;
        if (blockIdx.x == 0) { biasp = nullptr; }
        else { C = Calt; koff = koffAlt; }
    }

    const int lrow = t >> 1;
    const int lofs = (t & 1) * 8;
    const int aRow = m0 + lrow;
    const int aOK  = (aRow < M) ? 16 : 0;
    const int aRowC = (aRow < M) ? aRow : 0;
    const float* WhiRow = Whi + (size_t)(n0 + lrow) * K_TOT + koff;
    const float* WloRow = Wlo + (size_t)(n0 + lrow) * K_TOT + koff;

    float acc[2][8][4];
    #pragma unroll
    for (int mt = 0; mt < 2; mt++)
        #pragma unroll
        for (int nt = 0; nt < 8; nt++)
            #pragma unroll
            for (int q = 0; q < 4; q++) acc[mt][nt][q] = 0.f;

    uint32_t aSm[2], bhSm[2], blSm[2];
    #pragma unroll
    for (int bfi = 0; bfi < 2; bfi++) {
        uint32_t o = (uint32_t)(bfi * 2560 + lrow * 20 + lofs) * 4;
        aSm[bfi]  = (uint32_t)__cvta_generic_to_shared(AS) + o;
        bhSm[bfi] = (uint32_t)__cvta_generic_to_shared(BH) + o;
        blSm[bfi] = (uint32_t)__cvta_generic_to_shared(BL) + o;
    }

    auto load_stage = [&](int s, int bf) {
        const float* Asrc = (s < 32) ? A0 : A1;
        const int kcol = (s & 31) * 16;
        const float* ap = Asrc + (size_t)aRowC * 512 + kcol + lofs;
        cp_async16(aSm[bf],      ap,     aOK);
        cp_async16(aSm[bf] + 16, ap + 4, aOK);
        const float* hp = WhiRow + s * 16 + lofs;
        cp_async16(bhSm[bf],      hp,     16);
        cp_async16(bhSm[bf] + 16, hp + 4, 16);
        const float* lp = WloRow + s * 16 + lofs;
        cp_async16(blSm[bf],      lp,     16);
        cp_async16(blSm[bf] + 16, lp + 4, 16);
    };

    load_stage(0, 0);
    cp_commit();

    for (int s = 0; s < nstages; s++) {
        const int bf = s & 1;
        if (s + 1 < nstages) { load_stage(s + 1, bf ^ 1); cp_commit(); cp_wait<1>(); }
        else                 { cp_wait<0>(); }
        __syncthreads();

        const float* ASb = AS + bf * 2560;
        const float* BHb = BH + bf * 2560;
        const float* BLb = BL + bf * 2560;

        #pragma unroll
        for (int kk = 0; kk < 16; kk += 8) {
            uint32_t ah[2][4], al[2][4];
            #pragma unroll
            for (int mt = 0; mt < 2; mt++) {
                int r = warpM * 32 + mt * 16 + gid;
                tf32_split(ASb[r * 20 + kk + tig],            ah[mt][0], al[mt][0]);
                tf32_split(ASb[(r + 8) * 20 + kk + tig],      ah[mt][1], al[mt][1]);
                tf32_split(ASb[r * 20 + kk + tig + 4],        ah[mt][2], al[mt][2]);
                tf32_split(ASb[(r + 8) * 20 + kk + tig + 4],  ah[mt][3], al[mt][3]);
            }
            #pragma unroll
            for (int nt = 0; nt < 8; nt++) {
                int n = warpN * 64 + nt * 8 + gid;
                uint32_t bh[2], bl[2];
                bh[0] = __float_as_uint(BHb[n * 20 + kk + tig]);
                bh[1] = __float_as_uint(BHb[n * 20 + kk + tig + 4]);
                bl[0] = __float_as_uint(BLb[n * 20 + kk + tig]);
                bl[1] = __float_as_uint(BLb[n * 20 + kk + tig + 4]);
                #pragma unroll
                for (int mt = 0; mt < 2; mt++) {
                    mma_tf32(acc[mt][nt], al[mt], bh);  // lo*hi
                    mma_tf32(acc[mt][nt], ah[mt], bl);  // hi*lo
                    mma_tf32(acc[mt][nt], ah[mt], bh);  // hi*hi
                }
            }
        }
        __syncthreads();
    }

    #pragma unroll
    for (int nt = 0; nt < 8; nt++) {
        int cbase = n0 + warpN * 64 + nt * 8 + tig * 2;
        float b0 = biasp ? __ldg(&biasp[cbase])     : 0.f;
        float b1 = biasp ? __ldg(&biasp[cbase + 1]) : 0.f;
        #pragma unroll
        for (int mt = 0; mt < 2; mt++) {
            int r0 = m0 + warpM * 32 + mt * 16 + gid;
            int r1 = r0 + 8;
            float2 o0, o1;
            o0.x = acc[mt][nt][0] + b0; o0.y = acc[mt][nt][1] + b1;
            o1.x = acc[mt][nt][2] + b0; o1.y = acc[mt][nt][3] + b1;
            if (do_relu) {
                o0.x = fmaxf(o0.x, 0.f); o0.y = fmaxf(o0.y, 0.f);
                o1.x = fmaxf(o1.x, 0.f); o1.y = fmaxf(o1.y, 0.f);
            }
            if (r0 < M) *(float2*)(C + (size_t)r0 * N + cbase) = o0;
            if (r1 < M) *(float2*)(C + (size_t)r1 * N + cbase) = o1;
        }
    }
}

// ---------------------------------------------------------------------------
// Launch.  Inputs: h, W1, b1, W2, b2, src, dst
// out = h1 @ W2[0:512] + b2 + agg(h1 @ W2[512:1024])
// ---------------------------------------------------------------------------
extern "C" void kernel_launch(void* const* d_in, const int* in_sizes, int n_in,
                              void* d_out, int out_size) {
    const float* h   = (const float*)d_in[0];
    const float* W1  = (const float*)d_in[1];
    const float* b1  = (const float*)d_in[2];
    const float* W2  = (const float*)d_in[3];
    const float* b2  = (const float*)d_in[4];
    const int*   src = (const int*)d_in[5];
    const int*   dst = (const int*)d_in[6];
    float*       out = (float*)d_out;

    float *hN, *h1, *Y2, *P2, *W1tH, *W1tL, *W2tH, *W2tL;
    int *cnt, *cur;
    cudaGetSymbolAddress((void**)&hN,   g_hN);
    cudaGetSymbolAddress((void**)&h1,   g_h1);
    cudaGetSymbolAddress((void**)&Y2,   g_Y2);
    cudaGetSymbolAddress((void**)&P2,   g_P2);
    cudaGetSymbolAddress((void**)&W1tH, g_W1tH);
    cudaGetSymbolAddress((void**)&W1tL, g_W1tL);
    cudaGetSymbolAddress((void**)&W2tH, g_W2tH);
    cudaGetSymbolAddress((void**)&W2tL, g_W2tL);
    cudaGetSymbolAddress((void**)&cnt,  g_cnt);
    cudaGetSymbolAddress((void**)&cur,  g_cur);

    cudaFuncSetAttribute(gemm_mma_kernel,
                         cudaFuncAttributeMaxDynamicSharedMemorySize,
                         GEMM_SMEM_BYTES);

    const int TB = 256;

    // CSR build
    cudaMemsetAsync(cnt, 0, N_NODES * sizeof(int));
    cudaMemsetAsync(cur, 0, N_NODES * sizeof(int));
    count_kernel<<<(N_EDGES + TB - 1) / TB, TB>>>(dst);
    scan_kernel<<<1, 1024>>>();
    fill_kernel<<<(N_EDGES + TB - 1) / TB, TB>>>(src, dst);

    // Weight transpose + split
    {
        dim3 blk(32, 8);
        transpose_split_kernel<<<dim3(H_FEATS / 32, K_TOT / 32), blk>>>(W1, W1tH, W1tL, K_TOT, H_FEATS);
        transpose_split_kernel<<<dim3(N_CLASSES / 32, K_TOT / 32), blk>>>(W2, W2tH, W2tL, K_TOT, N_CLASSES);
    }

    const int MT = (N_NODES + 127) / 128;  // 79

    // Layer 1: h1 = relu([h, agg(h)] @ W1 + b1)
    agg512_kernel<<<N_NODES, 128>>>(h, hN);
    {
        dim3 grid(H_FEATS / 128, MT);
        gemm_mma_kernel<<<grid, 256, GEMM_SMEM_BYTES>>>(
            h, hN, W1tH, W1tL, b1, h1, nullptr,
            N_NODES, H_FEATS, 1, 64, 0, 0, 0);
    }

    // Layer 2 dual: block x=0 -> Y2 = h1 @ W2[512:], no bias
    //               block x=1 -> P2 = h1 @ W2[:512] + b2
    {
        dim3 grid(2, MT);
        gemm_mma_kernel<<<grid, 256, GEMM_SMEM_BYTES>>>(
            h1, nullptr, W2tH, W2tL, b2, Y2, P2,
            N_NODES, N_CLASSES, 0, 32, 512, 0, 1);
    }
    // out = P2 + agg(Y2)
    agg128_final_kernel<<<(N_NODES + 3) / 4, 128>>>(Y2, P2, out);
}

// round 8
// speedup vs baseline: 1.4741x; 1.4741x over previous
#include <cuda_runtime.h>
#include <cuda_bf16.h>
#include <stdint.h>

#define N_NODES   10000
#define N_EDGES   160000
#define F_IN      512
#define K_TOT     1024
#define H_FEATS   512
#define N_CLASSES 128
#define PK        (K_TOT / 2)   // 512 bf16-pairs per output row

// ---------------------------------------------------------------------------
// Device scratch
// ---------------------------------------------------------------------------
__device__ int   g_cnt[N_NODES];
__device__ int   g_cur[N_NODES];
__device__ int   g_off[N_NODES + 1];
__device__ int   g_adj[N_EDGES];
__device__ float g_hN [(size_t)N_NODES * F_IN];
__device__ float g_h1 [(size_t)N_NODES * H_FEATS];
__device__ float g_Y2 [(size_t)N_NODES * N_CLASSES];
__device__ float g_P2 [(size_t)N_NODES * N_CLASSES];
__device__ uint32_t g_W1ph[(size_t)H_FEATS   * PK];  // [n][pair] bf16x2 hi
__device__ uint32_t g_W1pl[(size_t)H_FEATS   * PK];  // bf16x2 lo
__device__ uint32_t g_W2ph[(size_t)N_CLASSES * PK];
__device__ uint32_t g_W2pl[(size_t)N_CLASSES * PK];

// ---------------------------------------------------------------------------
// helpers
// ---------------------------------------------------------------------------
__device__ __forceinline__ void cp_async16(uint32_t dst, const void* src, int src_bytes) {
    asm volatile("cp.async.cg.shared.global [%0], [%1], 16, %2;"
                 :: "r"(dst), "l"(src), "r"(src_bytes));
}
__device__ __forceinline__ void cp_commit() {
    asm volatile("cp.async.commit_group;" ::: "memory");
}
template <int N>
__device__ __forceinline__ void cp_wait() {
    asm volatile("cp.async.wait_group %0;" :: "n"(N) : "memory");
}
__device__ __forceinline__ void mma_bf16(float* c, const uint32_t* a, const uint32_t* b) {
    asm volatile(
        "mma.sync.aligned.m16n8k16.row.col.f32.bf16.bf16.f32 "
        "{%0,%1,%2,%3}, {%4,%5,%6,%7}, {%8,%9}, {%0,%1,%2,%3};"
        : "+f"(c[0]), "+f"(c[1]), "+f"(c[2]), "+f"(c[3])
        : "r"(a[0]), "r"(a[1]), "r"(a[2]), "r"(a[3]), "r"(b[0]), "r"(b[1]));
}
// pack: lower half = bf16(x0), upper half = bf16(x1)  (RN)
__device__ __forceinline__ uint32_t pack_bf16x2(float x0, float x1) {
    uint32_t r;
    asm("cvt.rn.bf16x2.f32 %0, %1, %2;" : "=r"(r) : "f"(x1), "f"(x0));
    return r;
}
// split a float2 (x0,x1) into packed hi + packed lo (exact residual)
__device__ __forceinline__ void split2_bf16(float x0, float x1, uint32_t& hi, uint32_t& lo) {
    hi = pack_bf16x2(x0, x1);
    float h0 = __uint_as_float(hi << 16);
    float h1 = __uint_as_float(hi & 0xFFFF0000u);
    lo = pack_bf16x2(x0 - h0, x1 - h1);
}

// ---------------------------------------------------------------------------
// CSR build
// ---------------------------------------------------------------------------
__global__ void count_kernel(const int* __restrict__ dst) {
    int e = blockIdx.x * blockDim.x + threadIdx.x;
    if (e < N_EDGES) atomicAdd(&g_cnt[dst[e]], 1);
}
__global__ void scan_kernel() {
    __shared__ int wsum[32];
    __shared__ int chunk_total;
    const int lane = threadIdx.x & 31;
    const int wid  = threadIdx.x >> 5;
    int running = 0;
    for (int base = 0; base < N_NODES; base += 1024) {
        int i = base + threadIdx.x;
        int v = (i < N_NODES) ? g_cnt[i] : 0;
        int s = v;
        #pragma unroll
        for (int o = 1; o < 32; o <<= 1) {
            int u = __shfl_up_sync(0xffffffffu, s, o);
            if (lane >= o) s += u;
        }
        if (lane == 31) wsum[wid] = s;
        __syncthreads();
        if (wid == 0) {
            int ws = wsum[lane];
            #pragma unroll
            for (int o = 1; o < 32; o <<= 1) {
                int u = __shfl_up_sync(0xffffffffu, ws, o);
                if (lane >= o) ws += u;
            }
            wsum[lane] = ws;
            if (lane == 31) chunk_total = ws;
        }
        __syncthreads();
        int wpref = (wid > 0) ? wsum[wid - 1] : 0;
        if (i < N_NODES) g_off[i] = running + wpref + s - v;
        running += chunk_total;
        __syncthreads();
    }
    if (threadIdx.x == 0) g_off[N_NODES] = running;
}
__global__ void fill_kernel(const int* __restrict__ src, const int* __restrict__ dst) {
    int e = blockIdx.x * blockDim.x + threadIdx.x;
    if (e < N_EDGES) {
        int d = dst[e];
        int p = atomicAdd(&g_cur[d], 1);
        g_adj[g_off[d] + p] = src[e];
    }
}

// ---------------------------------------------------------------------------
// Aggregations
// ---------------------------------------------------------------------------
__global__ void agg512_kernel(const float* __restrict__ H, float* __restrict__ out) {
    int n   = blockIdx.x;
    int st  = g_off[n];
    int deg = g_off[n + 1] - st;
    int c4  = threadIdx.x;
    float4 acc = make_float4(0.f, 0.f, 0.f, 0.f);
    int e = 0;
    for (; e + 1 < deg; e += 2) {
        int s0 = g_adj[st + e];
        int s1 = g_adj[st + e + 1];
        float4 v0 = *(const float4*)(H + (size_t)s0 * 512 + c4 * 4);
        float4 v1 = *(const float4*)(H + (size_t)s1 * 512 + c4 * 4);
        acc.x += v0.x + v1.x; acc.y += v0.y + v1.y;
        acc.z += v0.z + v1.z; acc.w += v0.w + v1.w;
    }
    if (e < deg) {
        int s0 = g_adj[st + e];
        float4 v0 = *(const float4*)(H + (size_t)s0 * 512 + c4 * 4);
        acc.x += v0.x; acc.y += v0.y; acc.z += v0.z; acc.w += v0.w;
    }
    float inv = (deg > 0) ? (1.0f / (float)deg) : 0.0f;
    acc.x *= inv; acc.y *= inv; acc.z *= inv; acc.w *= inv;
    *(float4*)(out + (size_t)n * 512 + c4 * 4) = acc;
}

// out[n] = P[n] + mean_{s in N(n)} Y[s]   (width 128)
__global__ void agg128_final_kernel(const float* __restrict__ Y,
                                    const float* __restrict__ P,
                                    float* __restrict__ out) {
    int n = blockIdx.x * 4 + (threadIdx.x >> 5);
    int lane = threadIdx.x & 31;
    if (n >= N_NODES) return;
    int st  = g_off[n];
    int deg = g_off[n + 1] - st;
    float4 acc = make_float4(0.f, 0.f, 0.f, 0.f);
    int e = 0;
    for (; e + 1 < deg; e += 2) {
        int s0 = g_adj[st + e];
        int s1 = g_adj[st + e + 1];
        float4 v0 = *(const float4*)(Y + (size_t)s0 * 128 + lane * 4);
        float4 v1 = *(const float4*)(Y + (size_t)s1 * 128 + lane * 4);
        acc.x += v0.x + v1.x; acc.y += v0.y + v1.y;
        acc.z += v0.z + v1.z; acc.w += v0.w + v1.w;
    }
    if (e < deg) {
        int s0 = g_adj[st + e];
        float4 v0 = *(const float4*)(Y + (size_t)s0 * 128 + lane * 4);
        acc.x += v0.x; acc.y += v0.y; acc.z += v0.z; acc.w += v0.w;
    }
    float inv = (deg > 0) ? (1.0f / (float)deg) : 0.0f;
    float4 p = *(const float4*)(P + (size_t)n * 128 + lane * 4);
    acc.x = acc.x * inv + p.x; acc.y = acc.y * inv + p.y;
    acc.z = acc.z * inv + p.z; acc.w = acc.w * inv + p.w;
    *(float4*)(out + (size_t)n * 128 + lane * 4) = acc;
}

// ---------------------------------------------------------------------------
// W pack: in[K][C] (k-major) -> Wph/Wpl [C][K/2] packed bf16x2 hi / lo
// block (32,8): tile = 64 k-rows x 32 cols
// ---------------------------------------------------------------------------
__global__ void pack_w_kernel(const float* __restrict__ W,
                              uint32_t* __restrict__ Wph, uint32_t* __restrict__ Wpl,
                              int C) {
    __shared__ float sh[64][33];
    int n0 = blockIdx.x * 32;
    int k0 = blockIdx.y * 64;
    int tx = threadIdx.x, ty = threadIdx.y;
    #pragma unroll
    for (int j = 0; j < 64; j += 8)
        sh[j + ty][tx] = W[(size_t)(k0 + j + ty) * C + n0 + tx];
    __syncthreads();
    // write: rows n (ty+j), 32 pairs (tx)
    #pragma unroll
    for (int j = 0; j < 32; j += 8) {
        int nl = ty + j;
        float x0 = sh[2 * tx][nl];
        float x1 = sh[2 * tx + 1][nl];
        uint32_t hi, lo;
        split2_bf16(x0, x1, hi, lo);
        size_t o = (size_t)(n0 + nl) * PK + (k0 >> 1) + tx;
        Wph[o] = hi;
        Wpl[o] = lo;
    }
}

// ---------------------------------------------------------------------------
// bf16x3 GEMM:  C[M,N] = concatK(A0,A1)[M, ns*32] @ Wrow^T + bias (+ReLU)
// block 128x128, BK=32, 3-stage cp.async ring (1 sync/stage), occ 2.
// A: f32 SMEM [128][36]; B: packed bf16x2 hi/lo [128 n][16 pairs], chunk-XOR swizzle.
// 8 warps (4 warpM x 2 warpN); warp tile 32x64 = 2x8 m16n8k16, 3 MMAs each.
// dual mode (gridDim.x==2, N=128): x=0 -> C,koffp ; x=1 -> Calt,koffpAlt,+bias.
// ---------------------------------------------------------------------------
#define AS_STRIDE   36
#define STAGE_A     (128 * AS_STRIDE)           // floats
#define STAGE_B     (128 * 16)                  // uint32 per buffer
#define STAGE_TOT   (STAGE_A + 2 * STAGE_B)     // 4608+4096 = 8704 words
#define GEMM_SMEM_BYTES (3 * STAGE_TOT * 4)     // 104448

__global__ __launch_bounds__(256, 2)
void gemm_bf16x3_kernel(const float* __restrict__ A0, const float* __restrict__ A1,
                        const uint32_t* __restrict__ Wph, const uint32_t* __restrict__ Wpl,
                        const float* __restrict__ bias,
                        float* __restrict__ C, float* __restrict__ Calt,
                        int M, int N, int do_relu, int nstages,
                        int koffp, int koffpAlt, int dual) {
    extern __shared__ float smem[];

    const int t     = threadIdx.x;
    const int lane  = t & 31;
    const int wid   = t >> 5;
    const int warpM = wid & 3;
    const int warpN = wid >> 2;
    const int gid   = lane >> 2;
    const int tig   = lane & 3;
    const int m0    = blockIdx.y * 128;

    int n0 = blockIdx.x * 128;
    const float* biasp = bias;
    if (dual) {
        n0 = 0;
        if (blockIdx.x == 0) biasp = nullptr;
        else { C = Calt; koffp = koffpAlt; }
    }

    // A loader: row = t>>1, 4 float4 chunks at (t&1)*16 + i*4
    const int lrow  = t >> 1;
    const int lhalf = (t & 1) * 16;
    const int aRow  = m0 + lrow;
    const int aOK   = (aRow < M) ? 16 : 0;
    const int aRowC = (aRow < M) ? aRow : 0;
    // B loader: row n = t>>1, 2 chunks (t&1)*2 + {0,1}, XOR swizzle by n&3
    const int bn    = t >> 1;
    const int bc0   = (t & 1) * 2;
    const uint32_t* WphRow = Wph + (size_t)(n0 + bn) * PK + koffp;
    const uint32_t* WplRow = Wpl + (size_t)(n0 + bn) * PK + koffp;

    float acc[2][8][4];
    #pragma unroll
    for (int mt = 0; mt < 2; mt++)
        #pragma unroll
        for (int nt = 0; nt < 8; nt++)
            #pragma unroll
            for (int q = 0; q < 4; q++) acc[mt][nt][q] = 0.f;

    const uint32_t smemBase = (uint32_t)__cvta_generic_to_shared(smem);

    auto load_stage = [&](int s, int bf) {
        uint32_t stB = smemBase + (uint32_t)(bf * STAGE_TOT) * 4;
        // A
        const float* Asrc = (s < 16) ? A0 : A1;
        const float* ap = Asrc + (size_t)aRowC * 512 + (s & 15) * 32 + lhalf;
        uint32_t ad = stB + (uint32_t)(lrow * AS_STRIDE + lhalf) * 4;
        #pragma unroll
        for (int i = 0; i < 4; i++)
            cp_async16(ad + i * 16, ap + i * 4, aOK);
        // B (hi, lo), chunk swizzle: chunk c -> c ^ (n&3)
        uint32_t bhB = stB + (uint32_t)STAGE_A * 4 + (uint32_t)(bn * 16) * 4;
        uint32_t blB = bhB + (uint32_t)STAGE_B * 4;
        #pragma unroll
        for (int i = 0; i < 2; i++) {
            int c  = bc0 + i;
            int sc = c ^ (bn & 3);
            cp_async16(bhB + sc * 16, WphRow + s * 16 + c * 4, 16);
            cp_async16(blB + sc * 16, WplRow + s * 16 + c * 4, 16);
        }
    };

    load_stage(0, 0); cp_commit();
    if (nstages > 1) { load_stage(1, 1); cp_commit(); }

    for (int s = 0; s < nstages; s++) {
        if (s + 1 < nstages) cp_wait<1>(); else cp_wait<0>();
        __syncthreads();
        int bf = s % 3;
        if (s + 2 < nstages) { load_stage(s + 2, (s + 2) % 3); cp_commit(); }

        const float*    ASb = smem + bf * STAGE_TOT;
        const uint32_t* BHb = (const uint32_t*)(smem + bf * STAGE_TOT + STAGE_A);
        const uint32_t* BLb = BHb + STAGE_B;

        #pragma unroll
        for (int w = 0; w < 2; w++) {           // two K=16 windows in BK=32
            uint32_t ah[2][4], al[2][4];
            #pragma unroll
            for (int mt = 0; mt < 2; mt++) {
                int r = warpM * 32 + mt * 16 + gid;
                float2 p0 = *(const float2*)(ASb + r * AS_STRIDE + w * 16 + 2 * tig);
                float2 p1 = *(const float2*)(ASb + (r + 8) * AS_STRIDE + w * 16 + 2 * tig);
                float2 p2 = *(const float2*)(ASb + r * AS_STRIDE + w * 16 + 2 * tig + 8);
                float2 p3 = *(const float2*)(ASb + (r + 8) * AS_STRIDE + w * 16 + 2 * tig + 8);
                split2_bf16(p0.x, p0.y, ah[mt][0], al[mt][0]);
                split2_bf16(p1.x, p1.y, ah[mt][1], al[mt][1]);
                split2_bf16(p2.x, p2.y, ah[mt][2], al[mt][2]);
                split2_bf16(p3.x, p3.y, ah[mt][3], al[mt][3]);
            }
            #pragma unroll
            for (int nt = 0; nt < 8; nt++) {
                int n = warpN * 64 + nt * 8 + gid;
                // pair indices within row: p = 8w + tig (chunk 2w) and 8w+tig+4 (chunk 2w+1)
                int sc0 = ((2 * w)     ^ (n & 3)) * 4 + tig;
                int sc1 = ((2 * w + 1) ^ (n & 3)) * 4 + tig;
                uint32_t bh[2], bl[2];
                bh[0] = BHb[n * 16 + sc0];
                bh[1] = BHb[n * 16 + sc1];
                bl[0] = BLb[n * 16 + sc0];
                bl[1] = BLb[n * 16 + sc1];
                #pragma unroll
                for (int mt = 0; mt < 2; mt++) {
                    mma_bf16(acc[mt][nt], al[mt], bh);  // lo*hi
                    mma_bf16(acc[mt][nt], ah[mt], bl);  // hi*lo
                    mma_bf16(acc[mt][nt], ah[mt], bh);  // hi*hi
                }
            }
        }
    }

    // epilogue
    #pragma unroll
    for (int nt = 0; nt < 8; nt++) {
        int cbase = n0 + warpN * 64 + nt * 8 + tig * 2;
        float b0 = biasp ? __ldg(&biasp[cbase])     : 0.f;
        float b1 = biasp ? __ldg(&biasp[cbase + 1]) : 0.f;
        #pragma unroll
        for (int mt = 0; mt < 2; mt++) {
            int r0 = m0 + warpM * 32 + mt * 16 + gid;
            int r1 = r0 + 8;
            float2 o0, o1;
            o0.x = acc[mt][nt][0] + b0; o0.y = acc[mt][nt][1] + b1;
            o1.x = acc[mt][nt][2] + b0; o1.y = acc[mt][nt][3] + b1;
            if (do_relu) {
                o0.x = fmaxf(o0.x, 0.f); o0.y = fmaxf(o0.y, 0.f);
                o1.x = fmaxf(o1.x, 0.f); o1.y = fmaxf(o1.y, 0.f);
            }
            if (r0 < M) *(float2*)(C + (size_t)r0 * N + cbase) = o0;
            if (r1 < M) *(float2*)(C + (size_t)r1 * N + cbase) = o1;
        }
    }
}

// ---------------------------------------------------------------------------
// Launch.  Inputs: h, W1, b1, W2, b2, src, dst
// out = h1 @ W2[0:512] + b2 + agg(h1 @ W2[512:1024])
// ---------------------------------------------------------------------------
extern "C" void kernel_launch(void* const* d_in, const int* in_sizes, int n_in,
                              void* d_out, int out_size) {
    const float* h   = (const float*)d_in[0];
    const float* W1  = (const float*)d_in[1];
    const float* b1  = (const float*)d_in[2];
    const float* W2  = (const float*)d_in[3];
    const float* b2  = (const float*)d_in[4];
    const int*   src = (const int*)d_in[5];
    const int*   dst = (const int*)d_in[6];
    float*       out = (float*)d_out;

    float *hN, *h1, *Y2, *P2;
    uint32_t *W1ph, *W1pl, *W2ph, *W2pl;
    int *cnt, *cur;
    cudaGetSymbolAddress((void**)&hN,   g_hN);
    cudaGetSymbolAddress((void**)&h1,   g_h1);
    cudaGetSymbolAddress((void**)&Y2,   g_Y2);
    cudaGetSymbolAddress((void**)&P2,   g_P2);
    cudaGetSymbolAddress((void**)&W1ph, g_W1ph);
    cudaGetSymbolAddress((void**)&W1pl, g_W1pl);
    cudaGetSymbolAddress((void**)&W2ph, g_W2ph);
    cudaGetSymbolAddress((void**)&W2pl, g_W2pl);
    cudaGetSymbolAddress((void**)&cnt,  g_cnt);
    cudaGetSymbolAddress((void**)&cur,  g_cur);

    cudaFuncSetAttribute(gemm_bf16x3_kernel,
                         cudaFuncAttributeMaxDynamicSharedMemorySize,
                         GEMM_SMEM_BYTES);

    const int TB = 256;

    // CSR build
    cudaMemsetAsync(cnt, 0, N_NODES * sizeof(int));
    cudaMemsetAsync(cur, 0, N_NODES * sizeof(int));
    count_kernel<<<(N_EDGES + TB - 1) / TB, TB>>>(dst);
    scan_kernel<<<1, 1024>>>();
    fill_kernel<<<(N_EDGES + TB - 1) / TB, TB>>>(src, dst);

    // Weight pack (transpose + bf16 hi/lo split)
    {
        dim3 blk(32, 8);
        pack_w_kernel<<<dim3(H_FEATS / 32,   K_TOT / 64), blk>>>(W1, W1ph, W1pl, H_FEATS);
        pack_w_kernel<<<dim3(N_CLASSES / 32, K_TOT / 64), blk>>>(W2, W2ph, W2pl, N_CLASSES);
    }

    const int MT = (N_NODES + 127) / 128;  // 79

    // Layer 1: h1 = relu([h, agg(h)] @ W1 + b1)
    agg512_kernel<<<N_NODES, 128>>>(h, hN);
    {
        dim3 grid(H_FEATS / 128, MT);
        gemm_bf16x3_kernel<<<grid, 256, GEMM_SMEM_BYTES>>>(
            h, hN, W1ph, W1pl, b1, h1, nullptr,
            N_NODES, H_FEATS, 1, 32, 0, 0, 0);
    }

    // Layer 2 dual: x=0 -> Y2 = h1 @ W2[512:] (koffp=256, no bias)
    //               x=1 -> P2 = h1 @ W2[:512] + b2
    {
        dim3 grid(2, MT);
        gemm_bf16x3_kernel<<<grid, 256, GEMM_SMEM_BYTES>>>(
            h1, h1, W2ph, W2pl, b2, Y2, P2,
            N_NODES, N_CLASSES, 0, 16, 256, 0, 1);
    }
    // out = P2 + agg(Y2)
    agg128_final_kernel<<<(N_NODES + 3) / 4, 128>>>(Y2, P2, out);
}

// round 9
// speedup vs baseline: 1.5507x; 1.0520x over previous
#include <cuda_runtime.h>
#include <cuda_bf16.h>
#include <stdint.h>

#define N_NODES   10000
#define N_EDGES   160000
#define F_IN      512
#define K_TOT     1024
#define H_FEATS   512
#define N_CLASSES 128
#define PK        (K_TOT / 2)    // 512 pairs per weight row
#define PKA       (F_IN / 2)     // 256 pairs per activation row

// ---------------------------------------------------------------------------
// Device scratch
// ---------------------------------------------------------------------------
__device__ int   g_cnt[N_NODES];
__device__ int   g_cur[N_NODES];
__device__ int   g_off[N_NODES + 1];
__device__ int   g_adj[N_EDGES];
__device__ float g_Y2 [(size_t)N_NODES * N_CLASSES];
__device__ float g_P2 [(size_t)N_NODES * N_CLASSES];
__device__ uint32_t g_hPh [(size_t)N_NODES * PKA];   // h packed bf16x2 hi
__device__ uint32_t g_hPl [(size_t)N_NODES * PKA];   // lo
__device__ uint32_t g_hNPh[(size_t)N_NODES * PKA];   // agg(h) packed
__device__ uint32_t g_hNPl[(size_t)N_NODES * PKA];
__device__ uint32_t g_h1Ph[(size_t)N_NODES * PKA];   // relu(layer1) packed
__device__ uint32_t g_h1Pl[(size_t)N_NODES * PKA];
__device__ uint32_t g_W1ph[(size_t)H_FEATS   * PK];
__device__ uint32_t g_W1pl[(size_t)H_FEATS   * PK];
__device__ uint32_t g_W2ph[(size_t)N_CLASSES * PK];
__device__ uint32_t g_W2pl[(size_t)N_CLASSES * PK];

// ---------------------------------------------------------------------------
// helpers
// ---------------------------------------------------------------------------
__device__ __forceinline__ void cp_async16(uint32_t dst, const void* src, int src_bytes) {
    asm volatile("cp.async.cg.shared.global [%0], [%1], 16, %2;"
                 :: "r"(dst), "l"(src), "r"(src_bytes));
}
__device__ __forceinline__ void cp_commit() {
    asm volatile("cp.async.commit_group;" ::: "memory");
}
template <int N>
__device__ __forceinline__ void cp_wait() {
    asm volatile("cp.async.wait_group %0;" :: "n"(N) : "memory");
}
__device__ __forceinline__ void mma_bf16(float* c, const uint32_t* a, const uint32_t* b) {
    asm volatile(
        "mma.sync.aligned.m16n8k16.row.col.f32.bf16.bf16.f32 "
        "{%0,%1,%2,%3}, {%4,%5,%6,%7}, {%8,%9}, {%0,%1,%2,%3};"
        : "+f"(c[0]), "+f"(c[1]), "+f"(c[2]), "+f"(c[3])
        : "r"(a[0]), "r"(a[1]), "r"(a[2]), "r"(a[3]), "r"(b[0]), "r"(b[1]));
}
__device__ __forceinline__ uint32_t pack_bf16x2(float x0, float x1) {
    uint32_t r;
    asm("cvt.rn.bf16x2.f32 %0, %1, %2;" : "=r"(r) : "f"(x1), "f"(x0));
    return r;
}
__device__ __forceinline__ void split2_bf16(float x0, float x1, uint32_t& hi, uint32_t& lo) {
    hi = pack_bf16x2(x0, x1);
    float h0 = __uint_as_float(hi << 16);
    float h1 = __uint_as_float(hi & 0xFFFF0000u);
    lo = pack_bf16x2(x0 - h0, x1 - h1);
}

// ---------------------------------------------------------------------------
// CSR build
// ---------------------------------------------------------------------------
__global__ void count_kernel(const int* __restrict__ dst) {
    int e = blockIdx.x * blockDim.x + threadIdx.x;
    if (e < N_EDGES) atomicAdd(&g_cnt[dst[e]], 1);
}
__global__ void scan_kernel() {
    __shared__ int wsum[32];
    __shared__ int chunk_total;
    const int lane = threadIdx.x & 31;
    const int wid  = threadIdx.x >> 5;
    int running = 0;
    for (int base = 0; base < N_NODES; base += 1024) {
        int i = base + threadIdx.x;
        int v = (i < N_NODES) ? g_cnt[i] : 0;
        int s = v;
        #pragma unroll
        for (int o = 1; o < 32; o <<= 1) {
            int u = __shfl_up_sync(0xffffffffu, s, o);
            if (lane >= o) s += u;
        }
        if (lane == 31) wsum[wid] = s;
        __syncthreads();
        if (wid == 0) {
            int ws = wsum[lane];
            #pragma unroll
            for (int o = 1; o < 32; o <<= 1) {
                int u = __shfl_up_sync(0xffffffffu, ws, o);
                if (lane >= o) ws += u;
            }
            wsum[lane] = ws;
            if (lane == 31) chunk_total = ws;
        }
        __syncthreads();
        int wpref = (wid > 0) ? wsum[wid - 1] : 0;
        if (i < N_NODES) g_off[i] = running + wpref + s - v;
        running += chunk_total;
        __syncthreads();
    }
    if (threadIdx.x == 0) g_off[N_NODES] = running;
}
__global__ void fill_kernel(const int* __restrict__ src, const int* __restrict__ dst) {
    int e = blockIdx.x * blockDim.x + threadIdx.x;
    if (e < N_EDGES) {
        int d = dst[e];
        int p = atomicAdd(&g_cur[d], 1);
        g_adj[g_off[d] + p] = src[e];
    }
}

// ---------------------------------------------------------------------------
// pack_h: h[N][512] f32 -> packed hi/lo pairs
// ---------------------------------------------------------------------------
__global__ void pack_h_kernel(const float* __restrict__ H,
                              uint32_t* __restrict__ Ph, uint32_t* __restrict__ Pl) {
    int i = blockIdx.x * blockDim.x + threadIdx.x;       // pair index
    if (i < N_NODES * PKA) {
        float2 v = ((const float2*)H)[i];
        uint32_t hi, lo;
        split2_bf16(v.x, v.y, hi, lo);
        Ph[i] = hi;
        Pl[i] = lo;
    }
}

// ---------------------------------------------------------------------------
// agg512 + pack: out = packed(mean of neighbor rows of H)
// ---------------------------------------------------------------------------
__global__ void agg512_pack_kernel(const float* __restrict__ H,
                                   uint32_t* __restrict__ Ph, uint32_t* __restrict__ Pl) {
    int n   = blockIdx.x;
    int st  = g_off[n];
    int deg = g_off[n + 1] - st;
    int c4  = threadIdx.x;
    float4 acc = make_float4(0.f, 0.f, 0.f, 0.f);
    int e = 0;
    for (; e + 1 < deg; e += 2) {
        int s0 = g_adj[st + e];
        int s1 = g_adj[st + e + 1];
        float4 v0 = *(const float4*)(H + (size_t)s0 * 512 + c4 * 4);
        float4 v1 = *(const float4*)(H + (size_t)s1 * 512 + c4 * 4);
        acc.x += v0.x + v1.x; acc.y += v0.y + v1.y;
        acc.z += v0.z + v1.z; acc.w += v0.w + v1.w;
    }
    if (e < deg) {
        int s0 = g_adj[st + e];
        float4 v0 = *(const float4*)(H + (size_t)s0 * 512 + c4 * 4);
        acc.x += v0.x; acc.y += v0.y; acc.z += v0.z; acc.w += v0.w;
    }
    float inv = (deg > 0) ? (1.0f / (float)deg) : 0.0f;
    acc.x *= inv; acc.y *= inv; acc.z *= inv; acc.w *= inv;
    uint32_t h0, l0, h1, l1;
    split2_bf16(acc.x, acc.y, h0, l0);
    split2_bf16(acc.z, acc.w, h1, l1);
    ((uint2*)(Ph + (size_t)n * PKA))[c4] = make_uint2(h0, h1);
    ((uint2*)(Pl + (size_t)n * PKA))[c4] = make_uint2(l0, l1);
}

// out[n] = P[n] + mean_{s in N(n)} Y[s]   (width 128)
__global__ void agg128_final_kernel(const float* __restrict__ Y,
                                    const float* __restrict__ P,
                                    float* __restrict__ out) {
    int n = blockIdx.x * 4 + (threadIdx.x >> 5);
    int lane = threadIdx.x & 31;
    if (n >= N_NODES) return;
    int st  = g_off[n];
    int deg = g_off[n + 1] - st;
    float4 acc = make_float4(0.f, 0.f, 0.f, 0.f);
    int e = 0;
    for (; e + 1 < deg; e += 2) {
        int s0 = g_adj[st + e];
        int s1 = g_adj[st + e + 1];
        float4 v0 = *(const float4*)(Y + (size_t)s0 * 128 + lane * 4);
        float4 v1 = *(const float4*)(Y + (size_t)s1 * 128 + lane * 4);
        acc.x += v0.x + v1.x; acc.y += v0.y + v1.y;
        acc.z += v0.z + v1.z; acc.w += v0.w + v1.w;
    }
    if (e < deg) {
        int s0 = g_adj[st + e];
        float4 v0 = *(const float4*)(Y + (size_t)s0 * 128 + lane * 4);
        acc.x += v0.x; acc.y += v0.y; acc.z += v0.z; acc.w += v0.w;
    }
    float inv = (deg > 0) ? (1.0f / (float)deg) : 0.0f;
    float4 p = *(const float4*)(P + (size_t)n * 128 + lane * 4);
    acc.x = acc.x * inv + p.x; acc.y = acc.y * inv + p.y;
    acc.z = acc.z * inv + p.z; acc.w = acc.w * inv + p.w;
    *(float4*)(out + (size_t)n * 128 + lane * 4) = acc;
}

// ---------------------------------------------------------------------------
// W pack: in[K][C] (k-major) -> Wph/Wpl [C][K/2] packed bf16x2 hi / lo
// ---------------------------------------------------------------------------
__global__ void pack_w_kernel(const float* __restrict__ W,
                              uint32_t* __restrict__ Wph, uint32_t* __restrict__ Wpl,
                              int C) {
    __shared__ float sh[64][33];
    int n0 = blockIdx.x * 32;
    int k0 = blockIdx.y * 64;
    int tx = threadIdx.x, ty = threadIdx.y;
    #pragma unroll
    for (int j = 0; j < 64; j += 8)
        sh[j + ty][tx] = W[(size_t)(k0 + j + ty) * C + n0 + tx];
    __syncthreads();
    #pragma unroll
    for (int j = 0; j < 32; j += 8) {
        int nl = ty + j;
        float x0 = sh[2 * tx][nl];
        float x1 = sh[2 * tx + 1][nl];
        uint32_t hi, lo;
        split2_bf16(x0, x1, hi, lo);
        size_t o = (size_t)(n0 + nl) * PK + (k0 >> 1) + tx;
        Wph[o] = hi;
        Wpl[o] = lo;
    }
}

// ---------------------------------------------------------------------------
// bf16x3 GEMM, ALL operands pre-packed (pure LDS + MMA inner loop):
// block 128x128, BK=32 (16 pairs), 2-stage cp.async, occ 2.
// SMEM per stage (uint32 words): AH[128][20] AL[128][20] BH[128][20] BL[128][20]
// stride 20 -> conflict-free fragment loads.  2 stages = 80KB.
// Output: f32 C (dual-capable) OR packed hi/lo (for layer-1 -> layer-2 chain).
// ---------------------------------------------------------------------------
#define TSTR     20
#define SEG      (128 * TSTR)          // words per tile buffer
#define STAGE_W  (4 * SEG)             // 10240 words per stage
#define GEMM_SMEM_BYTES (2 * STAGE_W * 4)   // 81920

__global__ __launch_bounds__(256, 2)
void gemm_packed_kernel(const uint32_t* __restrict__ AH0, const uint32_t* __restrict__ AL0,
                        const uint32_t* __restrict__ AH1, const uint32_t* __restrict__ AL1,
                        const uint32_t* __restrict__ Wph, const uint32_t* __restrict__ Wpl,
                        const float* __restrict__ bias,
                        float* __restrict__ C, float* __restrict__ Calt,
                        uint32_t* __restrict__ OutH, uint32_t* __restrict__ OutL,
                        int M, int N, int do_relu, int nstages,
                        int koffp, int koffpAlt, int dual) {
    extern __shared__ uint32_t smem[];

    const int t     = threadIdx.x;
    const int lane  = t & 31;
    const int wid   = t >> 5;
    const int warpM = wid & 3;
    const int warpN = wid >> 2;
    const int gid   = lane >> 2;
    const int tig   = lane & 3;
    const int m0    = blockIdx.y * 128;

    int n0 = blockIdx.x * 128;
    const float* biasp = bias;
    if (dual) {
        n0 = 0;
        if (blockIdx.x == 0) biasp = nullptr;
        else { C = Calt; koffp = koffpAlt; }
    }

    // loaders: thread -> (row = t>>1, half = t&1 -> 8 words)
    const int lrow  = t >> 1;
    const int lhw   = (t & 1) * 8;
    const int aRow  = m0 + lrow;
    const int aOK   = (aRow < M) ? 16 : 0;
    const int aRowC = (aRow < M) ? aRow : 0;
    const uint32_t* WphRow = Wph + (size_t)(n0 + lrow) * PK + koffp;
    const uint32_t* WplRow = Wpl + (size_t)(n0 + lrow) * PK + koffp;

    float acc[2][8][4];
    #pragma unroll
    for (int mt = 0; mt < 2; mt++)
        #pragma unroll
        for (int nt = 0; nt < 8; nt++)
            #pragma unroll
            for (int q = 0; q < 4; q++) acc[mt][nt][q] = 0.f;

    const uint32_t smemBase = (uint32_t)__cvta_generic_to_shared(smem);
    const uint32_t ldst = (uint32_t)(lrow * TSTR + lhw) * 4;

    auto load_stage = [&](int s, int bf) {
        uint32_t stB = smemBase + (uint32_t)(bf * STAGE_W) * 4;
        const uint32_t* AH = (s < 16) ? AH0 : AH1;
        const uint32_t* AL = (s < 16) ? AL0 : AL1;
        const int pb = (s & 15) * 16;
        const uint32_t* ah = AH + (size_t)aRowC * PKA + pb + lhw;
        const uint32_t* al = AL + (size_t)aRowC * PKA + pb + lhw;
        cp_async16(stB + ldst,                    ah,     aOK);
        cp_async16(stB + ldst + 16,               ah + 4, aOK);
        cp_async16(stB + SEG * 4 + ldst,          al,     aOK);
        cp_async16(stB + SEG * 4 + ldst + 16,     al + 4, aOK);
        const uint32_t* bh = WphRow + s * 16 + lhw;
        const uint32_t* bl = WplRow + s * 16 + lhw;
        cp_async16(stB + 2 * SEG * 4 + ldst,      bh,     16);
        cp_async16(stB + 2 * SEG * 4 + ldst + 16, bh + 4, 16);
        cp_async16(stB + 3 * SEG * 4 + ldst,      bl,     16);
        cp_async16(stB + 3 * SEG * 4 + ldst + 16, bl + 4, 16);
    };

    load_stage(0, 0);
    cp_commit();

    for (int s = 0; s < nstages; s++) {
        const int bf = s & 1;
        if (s + 1 < nstages) { load_stage(s + 1, bf ^ 1); cp_commit(); cp_wait<1>(); }
        else                 { cp_wait<0>(); }
        __syncthreads();

        const uint32_t* AHb = smem + bf * STAGE_W;
        const uint32_t* ALb = AHb + SEG;
        const uint32_t* BHb = AHb + 2 * SEG;
        const uint32_t* BLb = AHb + 3 * SEG;

        #pragma unroll
        for (int w = 0; w < 2; w++) {           // two K=16 windows
            uint32_t ah[2][4], al[2][4];
            #pragma unroll
            for (int mt = 0; mt < 2; mt++) {
                int r = warpM * 32 + mt * 16 + gid;
                int b0 = r * TSTR + w * 8 + tig;
                ah[mt][0] = AHb[b0];
                ah[mt][1] = AHb[b0 + 8 * TSTR];
                ah[mt][2] = AHb[b0 + 4];
                ah[mt][3] = AHb[b0 + 8 * TSTR + 4];
                al[mt][0] = ALb[b0];
                al[mt][1] = ALb[b0 + 8 * TSTR];
                al[mt][2] = ALb[b0 + 4];
                al[mt][3] = ALb[b0 + 8 * TSTR + 4];
            }
            #pragma unroll
            for (int nt = 0; nt < 8; nt++) {
                int n = warpN * 64 + nt * 8 + gid;
                int nb = n * TSTR + w * 8 + tig;
                uint32_t bh[2], bl[2];
                bh[0] = BHb[nb];
                bh[1] = BHb[nb + 4];
                bl[0] = BLb[nb];
                bl[1] = BLb[nb + 4];
                #pragma unroll
                for (int mt = 0; mt < 2; mt++) {
                    mma_bf16(acc[mt][nt], al[mt], bh);  // lo*hi
                    mma_bf16(acc[mt][nt], ah[mt], bl);  // hi*lo
                    mma_bf16(acc[mt][nt], ah[mt], bh);  // hi*hi
                }
            }
        }
        __syncthreads();
    }

    // ---- epilogue ----
    #pragma unroll
    for (int nt = 0; nt < 8; nt++) {
        int cbase = n0 + warpN * 64 + nt * 8 + tig * 2;
        float b0 = biasp ? __ldg(&biasp[cbase])     : 0.f;
        float b1 = biasp ? __ldg(&biasp[cbase + 1]) : 0.f;
        #pragma unroll
        for (int mt = 0; mt < 2; mt++) {
            int r0 = m0 + warpM * 32 + mt * 16 + gid;
            int r1 = r0 + 8;
            float2 o0, o1;
            o0.x = acc[mt][nt][0] + b0; o0.y = acc[mt][nt][1] + b1;
            o1.x = acc[mt][nt][2] + b0; o1.y = acc[mt][nt][3] + b1;
            if (do_relu) {
                o0.x = fmaxf(o0.x, 0.f); o0.y = fmaxf(o0.y, 0.f);
                o1.x = fmaxf(o1.x, 0.f); o1.y = fmaxf(o1.y, 0.f);
            }
            if (OutH) {
                int p = cbase >> 1;
                uint32_t hi, lo;
                if (r0 < M) {
                    split2_bf16(o0.x, o0.y, hi, lo);
                    OutH[(size_t)r0 * PKA + p] = hi;
                    OutL[(size_t)r0 * PKA + p] = lo;
                }
                if (r1 < M) {
                    split2_bf16(o1.x, o1.y, hi, lo);
                    OutH[(size_t)r1 * PKA + p] = hi;
                    OutL[(size_t)r1 * PKA + p] = lo;
                }
            } else {
                if (r0 < M) *(float2*)(C + (size_t)r0 * N + cbase) = o0;
                if (r1 < M) *(float2*)(C + (size_t)r1 * N + cbase) = o1;
            }
        }
    }
}

// ---------------------------------------------------------------------------
// Launch.  Inputs: h, W1, b1, W2, b2, src, dst
// out = h1 @ W2[0:512] + b2 + agg(h1 @ W2[512:1024])
// ---------------------------------------------------------------------------
extern "C" void kernel_launch(void* const* d_in, const int* in_sizes, int n_in,
                              void* d_out, int out_size) {
    const float* h   = (const float*)d_in[0];
    const float* W1  = (const float*)d_in[1];
    const float* b1  = (const float*)d_in[2];
    const float* W2  = (const float*)d_in[3];
    const float* b2  = (const float*)d_in[4];
    const int*   src = (const int*)d_in[5];
    const int*   dst = (const int*)d_in[6];
    float*       out = (float*)d_out;

    float *Y2, *P2;
    uint32_t *hPh, *hPl, *hNPh, *hNPl, *h1Ph, *h1Pl, *W1ph, *W1pl, *W2ph, *W2pl;
    int *cnt, *cur;
    cudaGetSymbolAddress((void**)&Y2,   g_Y2);
    cudaGetSymbolAddress((void**)&P2,   g_P2);
    cudaGetSymbolAddress((void**)&hPh,  g_hPh);
    cudaGetSymbolAddress((void**)&hPl,  g_hPl);
    cudaGetSymbolAddress((void**)&hNPh, g_hNPh);
    cudaGetSymbolAddress((void**)&hNPl, g_hNPl);
    cudaGetSymbolAddress((void**)&h1Ph, g_h1Ph);
    cudaGetSymbolAddress((void**)&h1Pl, g_h1Pl);
    cudaGetSymbolAddress((void**)&W1ph, g_W1ph);
    cudaGetSymbolAddress((void**)&W1pl, g_W1pl);
    cudaGetSymbolAddress((void**)&W2ph, g_W2ph);
    cudaGetSymbolAddress((void**)&W2pl, g_W2pl);
    cudaGetSymbolAddress((void**)&cnt,  g_cnt);
    cudaGetSymbolAddress((void**)&cur,  g_cur);

    cudaFuncSetAttribute(gemm_packed_kernel,
                         cudaFuncAttributeMaxDynamicSharedMemorySize,
                         GEMM_SMEM_BYTES);

    const int TB = 256;

    // CSR build
    cudaMemsetAsync(cnt, 0, N_NODES * sizeof(int));
    cudaMemsetAsync(cur, 0, N_NODES * sizeof(int));
    count_kernel<<<(N_EDGES + TB - 1) / TB, TB>>>(dst);
    scan_kernel<<<1, 1024>>>();
    fill_kernel<<<(N_EDGES + TB - 1) / TB, TB>>>(src, dst);

    // Weight + input packing
    {
        dim3 blk(32, 8);
        pack_w_kernel<<<dim3(H_FEATS / 32,   K_TOT / 64), blk>>>(W1, W1ph, W1pl, H_FEATS);
        pack_w_kernel<<<dim3(N_CLASSES / 32, K_TOT / 64), blk>>>(W2, W2ph, W2pl, N_CLASSES);
    }
    pack_h_kernel<<<(N_NODES * PKA + TB - 1) / TB, TB>>>(h, hPh, hPl);

    // agg(h) -> packed
    agg512_pack_kernel<<<N_NODES, 128>>>(h, hNPh, hNPl);

    const int MT = (N_NODES + 127) / 128;  // 79

    // Layer 1: h1P = packed(relu([h, agg(h)] @ W1 + b1))
    {
        dim3 grid(H_FEATS / 128, MT);
        gemm_packed_kernel<<<grid, 256, GEMM_SMEM_BYTES>>>(
            hPh, hPl, hNPh, hNPl, W1ph, W1pl, b1,
            nullptr, nullptr, h1Ph, h1Pl,
            N_NODES, H_FEATS, 1, 32, 0, 0, 0);
    }

    // Layer 2 dual: x=0 -> Y2 = h1 @ W2[512:] (koffp=256);  x=1 -> P2 = h1 @ W2[:512] + b2
    {
        dim3 grid(2, MT);
        gemm_packed_kernel<<<grid, 256, GEMM_SMEM_BYTES>>>(
            h1Ph, h1Pl, h1Ph, h1Pl, W2ph, W2pl, b2,
            Y2, P2, nullptr, nullptr,
            N_NODES, N_CLASSES, 0, 16, 256, 0, 1);
    }
    // out = P2 + agg(Y2)
    agg128_final_kernel<<<(N_NODES + 3) / 4, 128>>>(Y2, P2, out);
}

// round 10
// speedup vs baseline: 1.6006x; 1.0322x over previous
#include <cuda_runtime.h>
#include <cuda_bf16.h>
#include <stdint.h>

#define N_NODES   10000
#define N_EDGES   160000
#define F_IN      512
#define K_TOT     1024
#define H_FEATS   512
#define N_CLASSES 128
#define PK        (K_TOT / 2)    // 512 pairs per weight row
#define PKA       (F_IN / 2)     // 256 pairs per activation row

// ---------------------------------------------------------------------------
// Device scratch (BSS zero-init; g_cnt/g_cur re-zeroed by tail kernel each call)
// ---------------------------------------------------------------------------
__device__ int   g_cnt[N_NODES];
__device__ int   g_cur[N_NODES];
__device__ int   g_off[N_NODES + 1];
__device__ int   g_adj[N_EDGES];
__device__ float g_Y2 [(size_t)N_NODES * N_CLASSES];
__device__ float g_P2 [(size_t)N_NODES * N_CLASSES];
__device__ uint32_t g_hPh [(size_t)N_NODES * PKA];
__device__ uint32_t g_hPl [(size_t)N_NODES * PKA];
__device__ uint32_t g_hNPh[(size_t)N_NODES * PKA];
__device__ uint32_t g_hNPl[(size_t)N_NODES * PKA];
__device__ uint32_t g_h1Ph[(size_t)N_NODES * PKA];
__device__ uint32_t g_h1Pl[(size_t)N_NODES * PKA];
__device__ uint32_t g_W1ph[(size_t)H_FEATS   * PK];
__device__ uint32_t g_W1pl[(size_t)H_FEATS   * PK];
__device__ uint32_t g_W2ph[(size_t)N_CLASSES * PK];
__device__ uint32_t g_W2pl[(size_t)N_CLASSES * PK];

// ---------------------------------------------------------------------------
// helpers
// ---------------------------------------------------------------------------
__device__ __forceinline__ void cp_async16(uint32_t dst, const void* src, int src_bytes) {
    asm volatile("cp.async.cg.shared.global [%0], [%1], 16, %2;"
                 :: "r"(dst), "l"(src), "r"(src_bytes));
}
__device__ __forceinline__ void cp_commit() {
    asm volatile("cp.async.commit_group;" ::: "memory");
}
template <int N>
__device__ __forceinline__ void cp_wait() {
    asm volatile("cp.async.wait_group %0;" :: "n"(N) : "memory");
}
__device__ __forceinline__ void mma_bf16(float* c, const uint32_t* a, const uint32_t* b) {
    asm volatile(
        "mma.sync.aligned.m16n8k16.row.col.f32.bf16.bf16.f32 "
        "{%0,%1,%2,%3}, {%4,%5,%6,%7}, {%8,%9}, {%0,%1,%2,%3};"
        : "+f"(c[0]), "+f"(c[1]), "+f"(c[2]), "+f"(c[3])
        : "r"(a[0]), "r"(a[1]), "r"(a[2]), "r"(a[3]), "r"(b[0]), "r"(b[1]));
}
__device__ __forceinline__ uint32_t pack_bf16x2(float x0, float x1) {
    uint32_t r;
    asm("cvt.rn.bf16x2.f32 %0, %1, %2;" : "=r"(r) : "f"(x1), "f"(x0));
    return r;
}
__device__ __forceinline__ void split2_bf16(float x0, float x1, uint32_t& hi, uint32_t& lo) {
    hi = pack_bf16x2(x0, x1);
    float h0 = __uint_as_float(hi << 16);
    float h1 = __uint_as_float(hi & 0xFFFF0000u);
    lo = pack_bf16x2(x0 - h0, x1 - h1);
}

// ---------------------------------------------------------------------------
// CSR build  (g_cnt/g_cur pre-zeroed: BSS on first call, tail kernel after)
// ---------------------------------------------------------------------------
__global__ void count_kernel(const int* __restrict__ dst) {
    int e = blockIdx.x * blockDim.x + threadIdx.x;
    if (e < N_EDGES) atomicAdd(&g_cnt[dst[e]], 1);
}
__global__ void scan_kernel() {
    __shared__ int wsum[32];
    __shared__ int chunk_total;
    const int lane = threadIdx.x & 31;
    const int wid  = threadIdx.x >> 5;
    int running = 0;
    for (int base = 0; base < N_NODES; base += 1024) {
        int i = base + threadIdx.x;
        int v = (i < N_NODES) ? g_cnt[i] : 0;
        int s = v;
        #pragma unroll
        for (int o = 1; o < 32; o <<= 1) {
            int u = __shfl_up_sync(0xffffffffu, s, o);
            if (lane >= o) s += u;
        }
        if (lane == 31) wsum[wid] = s;
        __syncthreads();
        if (wid == 0) {
            int ws = wsum[lane];
            #pragma unroll
            for (int o = 1; o < 32; o <<= 1) {
                int u = __shfl_up_sync(0xffffffffu, ws, o);
                if (lane >= o) ws += u;
            }
            wsum[lane] = ws;
            if (lane == 31) chunk_total = ws;
        }
        __syncthreads();
        int wpref = (wid > 0) ? wsum[wid - 1] : 0;
        if (i < N_NODES) g_off[i] = running + wpref + s - v;
        running += chunk_total;
        __syncthreads();
    }
    if (threadIdx.x == 0) g_off[N_NODES] = running;
}
__global__ void fill_kernel(const int* __restrict__ src, const int* __restrict__ dst) {
    int e = blockIdx.x * blockDim.x + threadIdx.x;
    if (e < N_EDGES) {
        int d = dst[e];
        int p = atomicAdd(&g_cur[d], 1);
        g_adj[g_off[d] + p] = src[e];
    }
}

// ---------------------------------------------------------------------------
// Combined W pack: blocks bx<16 handle W1 (C=512), bx>=16 handle W2 (C=128)
// in[K][C] k-major -> [C][K/2] packed bf16x2 hi/lo
// ---------------------------------------------------------------------------
__global__ void pack_w_all_kernel(const float* __restrict__ W1,
                                  const float* __restrict__ W2) {
    __shared__ float sh[64][33];
    const bool isW1 = (blockIdx.x < 16);
    const float* W = isW1 ? W1 : W2;
    uint32_t* Wph = isW1 ? g_W1ph : g_W2ph;
    uint32_t* Wpl = isW1 ? g_W1pl : g_W2pl;
    const int C = isW1 ? H_FEATS : N_CLASSES;
    int n0 = (isW1 ? blockIdx.x : blockIdx.x - 16) * 32;
    int k0 = blockIdx.y * 64;
    int tx = threadIdx.x, ty = threadIdx.y;
    #pragma unroll
    for (int j = 0; j < 64; j += 8)
        sh[j + ty][tx] = W[(size_t)(k0 + j + ty) * C + n0 + tx];
    __syncthreads();
    #pragma unroll
    for (int j = 0; j < 32; j += 8) {
        int nl = ty + j;
        float x0 = sh[2 * tx][nl];
        float x1 = sh[2 * tx + 1][nl];
        uint32_t hi, lo;
        split2_bf16(x0, x1, hi, lo);
        size_t o = (size_t)(n0 + nl) * PK + (k0 >> 1) + tx;
        Wph[o] = hi;
        Wpl[o] = lo;
    }
}

// ---------------------------------------------------------------------------
// agg512 + pack both: block n packs h[n] AND packed-mean of neighbors
// ---------------------------------------------------------------------------
__global__ void agg512_pack2_kernel(const float* __restrict__ H) {
    int n   = blockIdx.x;
    int st  = g_off[n];
    int deg = g_off[n + 1] - st;
    int c4  = threadIdx.x;

    // pack own row (h -> hP)
    {
        float4 v = *(const float4*)(H + (size_t)n * 512 + c4 * 4);
        uint32_t h0, l0, h1, l1;
        split2_bf16(v.x, v.y, h0, l0);
        split2_bf16(v.z, v.w, h1, l1);
        ((uint2*)(g_hPh + (size_t)n * PKA))[c4] = make_uint2(h0, h1);
        ((uint2*)(g_hPl + (size_t)n * PKA))[c4] = make_uint2(l0, l1);
    }

    // aggregate neighbors -> hNP
    float4 acc = make_float4(0.f, 0.f, 0.f, 0.f);
    int e = 0;
    for (; e + 1 < deg; e += 2) {
        int s0 = g_adj[st + e];
        int s1 = g_adj[st + e + 1];
        float4 v0 = *(const float4*)(H + (size_t)s0 * 512 + c4 * 4);
        float4 v1 = *(const float4*)(H + (size_t)s1 * 512 + c4 * 4);
        acc.x += v0.x + v1.x; acc.y += v0.y + v1.y;
        acc.z += v0.z + v1.z; acc.w += v0.w + v1.w;
    }
    if (e < deg) {
        int s0 = g_adj[st + e];
        float4 v0 = *(const float4*)(H + (size_t)s0 * 512 + c4 * 4);
        acc.x += v0.x; acc.y += v0.y; acc.z += v0.z; acc.w += v0.w;
    }
    float inv = (deg > 0) ? (1.0f / (float)deg) : 0.0f;
    acc.x *= inv; acc.y *= inv; acc.z *= inv; acc.w *= inv;
    uint32_t h0, l0, h1, l1;
    split2_bf16(acc.x, acc.y, h0, l0);
    split2_bf16(acc.z, acc.w, h1, l1);
    ((uint2*)(g_hNPh + (size_t)n * PKA))[c4] = make_uint2(h0, h1);
    ((uint2*)(g_hNPl + (size_t)n * PKA))[c4] = make_uint2(l0, l1);
}

// out[n] = P[n] + mean Y[neigh]; also re-zeroes g_cnt/g_cur for the next call
__global__ void agg128_final_kernel(const float* __restrict__ Y,
                                    const float* __restrict__ P,
                                    float* __restrict__ out) {
    int gi = blockIdx.x * blockDim.x + threadIdx.x;
    if (gi < N_NODES) { g_cnt[gi] = 0; g_cur[gi] = 0; }

    int n = blockIdx.x * 4 + (threadIdx.x >> 5);
    int lane = threadIdx.x & 31;
    if (n >= N_NODES) return;
    int st  = g_off[n];
    int deg = g_off[n + 1] - st;
    float4 acc = make_float4(0.f, 0.f, 0.f, 0.f);
    int e = 0;
    for (; e + 1 < deg; e += 2) {
        int s0 = g_adj[st + e];
        int s1 = g_adj[st + e + 1];
        float4 v0 = *(const float4*)(Y + (size_t)s0 * 128 + lane * 4);
        float4 v1 = *(const float4*)(Y + (size_t)s1 * 128 + lane * 4);
        acc.x += v0.x + v1.x; acc.y += v0.y + v1.y;
        acc.z += v0.z + v1.z; acc.w += v0.w + v1.w;
    }
    if (e < deg) {
        int s0 = g_adj[st + e];
        float4 v0 = *(const float4*)(Y + (size_t)s0 * 128 + lane * 4);
        acc.x += v0.x; acc.y += v0.y; acc.z += v0.z; acc.w += v0.w;
    }
    float inv = (deg > 0) ? (1.0f / (float)deg) : 0.0f;
    float4 p = *(const float4*)(P + (size_t)n * 128 + lane * 4);
    acc.x = acc.x * inv + p.x; acc.y = acc.y * inv + p.y;
    acc.z = acc.z * inv + p.z; acc.w = acc.w * inv + p.w;
    *(float4*)(out + (size_t)n * 128 + lane * 4) = acc;
}

// ---------------------------------------------------------------------------
// bf16x3 GEMM, all operands pre-packed (pure LDS + MMA inner loop)
// block 128x128, BK=32 (16 pairs), 2-stage cp.async, occ 2, 80KB SMEM.
// ---------------------------------------------------------------------------
#define TSTR     20
#define SEG      (128 * TSTR)
#define STAGE_W  (4 * SEG)
#define GEMM_SMEM_BYTES (2 * STAGE_W * 4)   // 81920

__global__ __launch_bounds__(256, 2)
void gemm_packed_kernel(const uint32_t* __restrict__ AH0, const uint32_t* __restrict__ AL0,
                        const uint32_t* __restrict__ AH1, const uint32_t* __restrict__ AL1,
                        const uint32_t* __restrict__ Wph, const uint32_t* __restrict__ Wpl,
                        const float* __restrict__ bias,
                        float* __restrict__ C, float* __restrict__ Calt,
                        uint32_t* __restrict__ OutH, uint32_t* __restrict__ OutL,
                        int M, int N, int do_relu, int nstages,
                        int koffp, int koffpAlt, int dual) {
    extern __shared__ uint32_t smem[];

    const int t     = threadIdx.x;
    const int lane  = t & 31;
    const int wid   = t >> 5;
    const int warpM = wid & 3;
    const int warpN = wid >> 2;
    const int gid   = lane >> 2;
    const int tig   = lane & 3;
    const int m0    = blockIdx.y * 128;

    int n0 = blockIdx.x * 128;
    const float* biasp = bias;
    if (dual) {
        n0 = 0;
        if (blockIdx.x == 0) biasp = nullptr;
        else { C = Calt; koffp = koffpAlt; }
    }

    const int lrow  = t >> 1;
    const int lhw   = (t & 1) * 8;
    const int aRow  = m0 + lrow;
    const int aOK   = (aRow < M) ? 16 : 0;
    const int aRowC = (aRow < M) ? aRow : 0;
    const uint32_t* WphRow = Wph + (size_t)(n0 + lrow) * PK + koffp;
    const uint32_t* WplRow = Wpl + (size_t)(n0 + lrow) * PK + koffp;

    float acc[2][8][4];
    #pragma unroll
    for (int mt = 0; mt < 2; mt++)
        #pragma unroll
        for (int nt = 0; nt < 8; nt++)
            #pragma unroll
            for (int q = 0; q < 4; q++) acc[mt][nt][q] = 0.f;

    const uint32_t smemBase = (uint32_t)__cvta_generic_to_shared(smem);
    const uint32_t ldst = (uint32_t)(lrow * TSTR + lhw) * 4;

    auto load_stage = [&](int s, int bf) {
        uint32_t stB = smemBase + (uint32_t)(bf * STAGE_W) * 4;
        const uint32_t* AH = (s < 16) ? AH0 : AH1;
        const uint32_t* AL = (s < 16) ? AL0 : AL1;
        const int pb = (s & 15) * 16;
        const uint32_t* ah = AH + (size_t)aRowC * PKA + pb + lhw;
        const uint32_t* al = AL + (size_t)aRowC * PKA + pb + lhw;
        cp_async16(stB + ldst,                    ah,     aOK);
        cp_async16(stB + ldst + 16,               ah + 4, aOK);
        cp_async16(stB + SEG * 4 + ldst,          al,     aOK);
        cp_async16(stB + SEG * 4 + ldst + 16,     al + 4, aOK);
        const uint32_t* bh = WphRow + s * 16 + lhw;
        const uint32_t* bl = WplRow + s * 16 + lhw;
        cp_async16(stB + 2 * SEG * 4 + ldst,      bh,     16);
        cp_async16(stB + 2 * SEG * 4 + ldst + 16, bh + 4, 16);
        cp_async16(stB + 3 * SEG * 4 + ldst,      bl,     16);
        cp_async16(stB + 3 * SEG * 4 + ldst + 16, bl + 4, 16);
    };

    load_stage(0, 0);
    cp_commit();

    for (int s = 0; s < nstages; s++) {
        const int bf = s & 1;
        if (s + 1 < nstages) { load_stage(s + 1, bf ^ 1); cp_commit(); cp_wait<1>(); }
        else                 { cp_wait<0>(); }
        __syncthreads();

        const uint32_t* AHb = smem + bf * STAGE_W;
        const uint32_t* ALb = AHb + SEG;
        const uint32_t* BHb = AHb + 2 * SEG;
        const uint32_t* BLb = AHb + 3 * SEG;

        #pragma unroll
        for (int w = 0; w < 2; w++) {
            uint32_t ah[2][4], al[2][4];
            #pragma unroll
            for (int mt = 0; mt < 2; mt++) {
                int r = warpM * 32 + mt * 16 + gid;
                int b0 = r * TSTR + w * 8 + tig;
                ah[mt][0] = AHb[b0];
                ah[mt][1] = AHb[b0 + 8 * TSTR];
                ah[mt][2] = AHb[b0 + 4];
                ah[mt][3] = AHb[b0 + 8 * TSTR + 4];
                al[mt][0] = ALb[b0];
                al[mt][1] = ALb[b0 + 8 * TSTR];
                al[mt][2] = ALb[b0 + 4];
                al[mt][3] = ALb[b0 + 8 * TSTR + 4];
            }
            #pragma unroll
            for (int nt = 0; nt < 8; nt++) {
                int n = warpN * 64 + nt * 8 + gid;
                int nb = n * TSTR + w * 8 + tig;
                uint32_t bh[2], bl[2];
                bh[0] = BHb[nb];
                bh[1] = BHb[nb + 4];
                bl[0] = BLb[nb];
                bl[1] = BLb[nb + 4];
                #pragma unroll
                for (int mt = 0; mt < 2; mt++) {
                    mma_bf16(acc[mt][nt], al[mt], bh);
                    mma_bf16(acc[mt][nt], ah[mt], bl);
                    mma_bf16(acc[mt][nt], ah[mt], bh);
                }
            }
        }
        __syncthreads();
    }

    #pragma unroll
    for (int nt = 0; nt < 8; nt++) {
        int cbase = n0 + warpN * 64 + nt * 8 + tig * 2;
        float b0 = biasp ? __ldg(&biasp[cbase])     : 0.f;
        float b1 = biasp ? __ldg(&biasp[cbase + 1]) : 0.f;
        #pragma unroll
        for (int mt = 0; mt < 2; mt++) {
            int r0 = m0 + warpM * 32 + mt * 16 + gid;
            int r1 = r0 + 8;
            float2 o0, o1;
            o0.x = acc[mt][nt][0] + b0; o0.y = acc[mt][nt][1] + b1;
            o1.x = acc[mt][nt][2] + b0; o1.y = acc[mt][nt][3] + b1;
            if (do_relu) {
                o0.x = fmaxf(o0.x, 0.f); o0.y = fmaxf(o0.y, 0.f);
                o1.x = fmaxf(o1.x, 0.f); o1.y = fmaxf(o1.y, 0.f);
            }
            if (OutH) {
                int p = cbase >> 1;
                uint32_t hi, lo;
                if (r0 < M) {
                    split2_bf16(o0.x, o0.y, hi, lo);
                    OutH[(size_t)r0 * PKA + p] = hi;
                    OutL[(size_t)r0 * PKA + p] = lo;
                }
                if (r1 < M) {
                    split2_bf16(o1.x, o1.y, hi, lo);
                    OutH[(size_t)r1 * PKA + p] = hi;
                    OutL[(size_t)r1 * PKA + p] = lo;
                }
            } else {
                if (r0 < M) *(float2*)(C + (size_t)r0 * N + cbase) = o0;
                if (r1 < M) *(float2*)(C + (size_t)r1 * N + cbase) = o1;
            }
        }
    }
}

// ---------------------------------------------------------------------------
// Launch.  Inputs: h, W1, b1, W2, b2, src, dst
// out = h1 @ W2[0:512] + b2 + agg(h1 @ W2[512:1024])
// Launch order puts GEMM1 at index 5 (ncu -s 5 -c 1 captures it).
// ---------------------------------------------------------------------------
extern "C" void kernel_launch(void* const* d_in, const int* in_sizes, int n_in,
                              void* d_out, int out_size) {
    const float* h   = (const float*)d_in[0];
    const float* W1  = (const float*)d_in[1];
    const float* b1  = (const float*)d_in[2];
    const float* W2  = (const float*)d_in[3];
    const float* b2  = (const float*)d_in[4];
    const int*   src = (const int*)d_in[5];
    const int*   dst = (const int*)d_in[6];
    float*       out = (float*)d_out;

    float *Y2, *P2;
    uint32_t *hPh, *hPl, *hNPh, *hNPl, *h1Ph, *h1Pl, *W1ph, *W1pl, *W2ph, *W2pl;
    cudaGetSymbolAddress((void**)&Y2,   g_Y2);
    cudaGetSymbolAddress((void**)&P2,   g_P2);
    cudaGetSymbolAddress((void**)&hPh,  g_hPh);
    cudaGetSymbolAddress((void**)&hPl,  g_hPl);
    cudaGetSymbolAddress((void**)&hNPh, g_hNPh);
    cudaGetSymbolAddress((void**)&hNPl, g_hNPl);
    cudaGetSymbolAddress((void**)&h1Ph, g_h1Ph);
    cudaGetSymbolAddress((void**)&h1Pl, g_h1Pl);
    cudaGetSymbolAddress((void**)&W1ph, g_W1ph);
    cudaGetSymbolAddress((void**)&W1pl, g_W1pl);
    cudaGetSymbolAddress((void**)&W2ph, g_W2ph);
    cudaGetSymbolAddress((void**)&W2pl, g_W2pl);

    cudaFuncSetAttribute(gemm_packed_kernel,
                         cudaFuncAttributeMaxDynamicSharedMemorySize,
                         GEMM_SMEM_BYTES);

    const int TB = 256;
    const int MT = (N_NODES + 127) / 128;  // 79

    // 0-2: CSR build (cnt/cur are zero: BSS on call 1, tail kernel thereafter)
    count_kernel<<<(N_EDGES + TB - 1) / TB, TB>>>(dst);
    scan_kernel<<<1, 1024>>>();
    fill_kernel<<<(N_EDGES + TB - 1) / TB, TB>>>(src, dst);

    // 3: both weight packs in one launch
    pack_w_all_kernel<<<dim3(20, K_TOT / 64), dim3(32, 8)>>>(W1, W2);

    // 4: agg(h)->packed + pack(h)
    agg512_pack2_kernel<<<N_NODES, 128>>>(h);

    // 5: Layer 1 GEMM  (profiled launch)
    {
        dim3 grid(H_FEATS / 128, MT);
        gemm_packed_kernel<<<grid, 256, GEMM_SMEM_BYTES>>>(
            hPh, hPl, hNPh, hNPl, W1ph, W1pl, b1,
            nullptr, nullptr, h1Ph, h1Pl,
            N_NODES, H_FEATS, 1, 32, 0, 0, 0);
    }

    // 6: Layer 2 dual GEMM
    {
        dim3 grid(2, MT);
        gemm_packed_kernel<<<grid, 256, GEMM_SMEM_BYTES>>>(
            h1Ph, h1Pl, h1Ph, h1Pl, W2ph, W2pl, b2,
            Y2, P2, nullptr, nullptr,
            N_NODES, N_CLASSES, 0, 16, 256, 0, 1);
    }

    // 7: out = P2 + agg(Y2); re-zero cnt/cur for next call
    agg128_final_kernel<<<(N_NODES + 3) / 4, 128>>>(Y2, P2, out);
}

// round 11
// speedup vs baseline: 1.6201x; 1.0122x over previous
#include <cuda_runtime.h>
#include <cuda_bf16.h>
#include <stdint.h>

#define N_NODES   10000
#define N_EDGES   160000
#define F_IN      512
#define K_TOT     1024
#define H_FEATS   512
#define N_CLASSES 128
#define PK        (K_TOT / 2)
#define PKA       (F_IN / 2)

// ---------------------------------------------------------------------------
// Device scratch (BSS zero-init; g_cnt/g_cur re-zeroed by tail kernel)
// ---------------------------------------------------------------------------
__device__ int   g_cnt[N_NODES];
__device__ int   g_cur[N_NODES];
__device__ int   g_off[N_NODES + 1];
__device__ int   g_adj[N_EDGES];
__device__ float g_Y2 [(size_t)N_NODES * N_CLASSES];
__device__ float g_P2 [(size_t)N_NODES * N_CLASSES];
__device__ uint32_t g_hPh [(size_t)N_NODES * PKA];
__device__ uint32_t g_hPl [(size_t)N_NODES * PKA];
__device__ uint32_t g_hNPh[(size_t)N_NODES * PKA];
__device__ uint32_t g_hNPl[(size_t)N_NODES * PKA];
__device__ uint32_t g_h1Ph[(size_t)N_NODES * PKA];
__device__ uint32_t g_h1Pl[(size_t)N_NODES * PKA];
__device__ uint32_t g_W1ph[(size_t)H_FEATS   * PK];
__device__ uint32_t g_W1pl[(size_t)H_FEATS   * PK];
__device__ uint32_t g_W2ph[(size_t)N_CLASSES * PK];
__device__ uint32_t g_W2pl[(size_t)N_CLASSES * PK];

// ---------------------------------------------------------------------------
// helpers
// ---------------------------------------------------------------------------
__device__ __forceinline__ void cp_async16(uint32_t dst, const void* src, int src_bytes) {
    asm volatile("cp.async.cg.shared.global [%0], [%1], 16, %2;"
                 :: "r"(dst), "l"(src), "r"(src_bytes));
}
__device__ __forceinline__ void cp_commit() {
    asm volatile("cp.async.commit_group;" ::: "memory");
}
template <int N>
__device__ __forceinline__ void cp_wait() {
    asm volatile("cp.async.wait_group %0;" :: "n"(N) : "memory");
}
__device__ __forceinline__ void mma_bf16(float* c, const uint32_t* a, const uint32_t* b) {
    asm volatile(
        "mma.sync.aligned.m16n8k16.row.col.f32.bf16.bf16.f32 "
        "{%0,%1,%2,%3}, {%4,%5,%6,%7}, {%8,%9}, {%0,%1,%2,%3};"
        : "+f"(c[0]), "+f"(c[1]), "+f"(c[2]), "+f"(c[3])
        : "r"(a[0]), "r"(a[1]), "r"(a[2]), "r"(a[3]), "r"(b[0]), "r"(b[1]));
}
__device__ __forceinline__ uint32_t pack_bf16x2(float x0, float x1) {
    uint32_t r;
    asm("cvt.rn.bf16x2.f32 %0, %1, %2;" : "=r"(r) : "f"(x1), "f"(x0));
    return r;
}
__device__ __forceinline__ void split2_bf16(float x0, float x1, uint32_t& hi, uint32_t& lo) {
    hi = pack_bf16x2(x0, x1);
    float h0 = __uint_as_float(hi << 16);
    float h1 = __uint_as_float(hi & 0xFFFF0000u);
    lo = pack_bf16x2(x0 - h0, x1 - h1);
}

// ---------------------------------------------------------------------------
// CSR build
// ---------------------------------------------------------------------------
__global__ void count_kernel(const int* __restrict__ dst) {
    int e = blockIdx.x * blockDim.x + threadIdx.x;
    if (e < N_EDGES) atomicAdd(&g_cnt[dst[e]], 1);
}
__global__ void scan_kernel() {
    __shared__ int wsum[32];
    __shared__ int chunk_total;
    const int lane = threadIdx.x & 31;
    const int wid  = threadIdx.x >> 5;
    int running = 0;
    for (int base = 0; base < N_NODES; base += 1024) {
        int i = base + threadIdx.x;
        int v = (i < N_NODES) ? g_cnt[i] : 0;
        int s = v;
        #pragma unroll
        for (int o = 1; o < 32; o <<= 1) {
            int u = __shfl_up_sync(0xffffffffu, s, o);
            if (lane >= o) s += u;
        }
        if (lane == 31) wsum[wid] = s;
        __syncthreads();
        if (wid == 0) {
            int ws = wsum[lane];
            #pragma unroll
            for (int o = 1; o < 32; o <<= 1) {
                int u = __shfl_up_sync(0xffffffffu, ws, o);
                if (lane >= o) ws += u;
            }
            wsum[lane] = ws;
            if (lane == 31) chunk_total = ws;
        }
        __syncthreads();
        int wpref = (wid > 0) ? wsum[wid - 1] : 0;
        if (i < N_NODES) g_off[i] = running + wpref + s - v;
        running += chunk_total;
        __syncthreads();
    }
    if (threadIdx.x == 0) g_off[N_NODES] = running;
}
__global__ void fill_kernel(const int* __restrict__ src, const int* __restrict__ dst) {
    int e = blockIdx.x * blockDim.x + threadIdx.x;
    if (e < N_EDGES) {
        int d = dst[e];
        int p = atomicAdd(&g_cur[d], 1);
        g_adj[g_off[d] + p] = src[e];
    }
}

// ---------------------------------------------------------------------------
// Combined W pack
// ---------------------------------------------------------------------------
__global__ void pack_w_all_kernel(const float* __restrict__ W1,
                                  const float* __restrict__ W2) {
    __shared__ float sh[64][33];
    const bool isW1 = (blockIdx.x < 16);
    const float* W = isW1 ? W1 : W2;
    uint32_t* Wph = isW1 ? g_W1ph : g_W2ph;
    uint32_t* Wpl = isW1 ? g_W1pl : g_W2pl;
    const int C = isW1 ? H_FEATS : N_CLASSES;
    int n0 = (isW1 ? blockIdx.x : blockIdx.x - 16) * 32;
    int k0 = blockIdx.y * 64;
    int tx = threadIdx.x, ty = threadIdx.y;
    #pragma unroll
    for (int j = 0; j < 64; j += 8)
        sh[j + ty][tx] = W[(size_t)(k0 + j + ty) * C + n0 + tx];
    __syncthreads();
    #pragma unroll
    for (int j = 0; j < 32; j += 8) {
        int nl = ty + j;
        float x0 = sh[2 * tx][nl];
        float x1 = sh[2 * tx + 1][nl];
        uint32_t hi, lo;
        split2_bf16(x0, x1, hi, lo);
        size_t o = (size_t)(n0 + nl) * PK + (k0 >> 1) + tx;
        Wph[o] = hi;
        Wpl[o] = lo;
    }
}

// ---------------------------------------------------------------------------
// agg512 + pack both
// ---------------------------------------------------------------------------
__global__ void agg512_pack2_kernel(const float* __restrict__ H) {
    int n   = blockIdx.x;
    int st  = g_off[n];
    int deg = g_off[n + 1] - st;
    int c4  = threadIdx.x;

    {
        float4 v = *(const float4*)(H + (size_t)n * 512 + c4 * 4);
        uint32_t h0, l0, h1, l1;
        split2_bf16(v.x, v.y, h0, l0);
        split2_bf16(v.z, v.w, h1, l1);
        ((uint2*)(g_hPh + (size_t)n * PKA))[c4] = make_uint2(h0, h1);
        ((uint2*)(g_hPl + (size_t)n * PKA))[c4] = make_uint2(l0, l1);
    }

    float4 acc = make_float4(0.f, 0.f, 0.f, 0.f);
    int e = 0;
    for (; e + 1 < deg; e += 2) {
        int s0 = g_adj[st + e];
        int s1 = g_adj[st + e + 1];
        float4 v0 = *(const float4*)(H + (size_t)s0 * 512 + c4 * 4);
        float4 v1 = *(const float4*)(H + (size_t)s1 * 512 + c4 * 4);
        acc.x += v0.x + v1.x; acc.y += v0.y + v1.y;
        acc.z += v0.z + v1.z; acc.w += v0.w + v1.w;
    }
    if (e < deg) {
        int s0 = g_adj[st + e];
        float4 v0 = *(const float4*)(H + (size_t)s0 * 512 + c4 * 4);
        acc.x += v0.x; acc.y += v0.y; acc.z += v0.z; acc.w += v0.w;
    }
    float inv = (deg > 0) ? (1.0f / (float)deg) : 0.0f;
    acc.x *= inv; acc.y *= inv; acc.z *= inv; acc.w *= inv;
    uint32_t h0, l0, h1, l1;
    split2_bf16(acc.x, acc.y, h0, l0);
    split2_bf16(acc.z, acc.w, h1, l1);
    ((uint2*)(g_hNPh + (size_t)n * PKA))[c4] = make_uint2(h0, h1);
    ((uint2*)(g_hNPl + (size_t)n * PKA))[c4] = make_uint2(l0, l1);
}

// out[n] = P[n] + mean Y[neigh]; re-zero cnt/cur
__global__ void agg128_final_kernel(const float* __restrict__ Y,
                                    const float* __restrict__ P,
                                    float* __restrict__ out) {
    int gi = blockIdx.x * blockDim.x + threadIdx.x;
    if (gi < N_NODES) { g_cnt[gi] = 0; g_cur[gi] = 0; }

    int n = blockIdx.x * 4 + (threadIdx.x >> 5);
    int lane = threadIdx.x & 31;
    if (n >= N_NODES) return;
    int st  = g_off[n];
    int deg = g_off[n + 1] - st;
    float4 acc = make_float4(0.f, 0.f, 0.f, 0.f);
    int e = 0;
    for (; e + 1 < deg; e += 2) {
        int s0 = g_adj[st + e];
        int s1 = g_adj[st + e + 1];
        float4 v0 = *(const float4*)(Y + (size_t)s0 * 128 + lane * 4);
        float4 v1 = *(const float4*)(Y + (size_t)s1 * 128 + lane * 4);
        acc.x += v0.x + v1.x; acc.y += v0.y + v1.y;
        acc.z += v0.z + v1.z; acc.w += v0.w + v1.w;
    }
    if (e < deg) {
        int s0 = g_adj[st + e];
        float4 v0 = *(const float4*)(Y + (size_t)s0 * 128 + lane * 4);
        acc.x += v0.x; acc.y += v0.y; acc.z += v0.z; acc.w += v0.w;
    }
    float inv = (deg > 0) ? (1.0f / (float)deg) : 0.0f;
    float4 p = *(const float4*)(P + (size_t)n * 128 + lane * 4);
    acc.x = acc.x * inv + p.x; acc.y = acc.y * inv + p.y;
    acc.z = acc.z * inv + p.z; acc.w = acc.w * inv + p.w;
    *(float4*)(out + (size_t)n * 128 + lane * 4) = acc;
}

// ---------------------------------------------------------------------------
// bf16x3 GEMM, templated on NT (warp N-tiles): block = 128 x (16*NT)
// NT=4: 128x64 tile, acc 32 regs, occ 3.  NT=8: 128x128 tile, occ 2 (dual-capable).
// ---------------------------------------------------------------------------
#define TSTR 20
#define A_SEG (128 * TSTR)

template <int NT, bool DUAL>
__device__ __forceinline__ void gemm_body(
        const uint32_t* __restrict__ AH0, const uint32_t* __restrict__ AL0,
        const uint32_t* __restrict__ AH1, const uint32_t* __restrict__ AL1,
        const uint32_t* __restrict__ Wph, const uint32_t* __restrict__ Wpl,
        const float* __restrict__ bias,
        float* __restrict__ C, float* __restrict__ Calt,
        uint32_t* __restrict__ OutH, uint32_t* __restrict__ OutL,
        int M, int N, int do_relu, int nstages, int koffp, int koffpAlt) {
    extern __shared__ uint32_t smem[];

    constexpr int BN    = 16 * NT;          // block N
    constexpr int B_SEG = BN * TSTR;
    constexpr int STAGE_W = 2 * A_SEG + 2 * B_SEG;

    const int t     = threadIdx.x;
    const int lane  = t & 31;
    const int wid   = t >> 5;
    const int warpM = wid & 3;
    const int warpN = wid >> 2;
    const int gid   = lane >> 2;
    const int tig   = lane & 3;
    const int m0    = blockIdx.y * 128;

    int n0 = blockIdx.x * BN;
    const float* biasp = bias;
    if (DUAL) {
        n0 = 0;
        if (blockIdx.x == 0) biasp = nullptr;
        else { C = Calt; koffp = koffpAlt; }
    }

    // A loader: row = t>>1 (128 rows), 8 words at (t&1)*8
    const int lrow  = t >> 1;
    const int lhw   = (t & 1) * 8;
    const int aRow  = m0 + lrow;
    const int aOK   = (aRow < M) ? 16 : 0;
    const int aRowC = (aRow < M) ? aRow : 0;
    // B loader
    //  NT=8: row = t>>1 (128 rows), 8 words at (t&1)*8 (2 cp per buf)
    //  NT=4: row = t>>2 (64 rows), 4 words at (t&3)*4 (1 cp per buf)
    const int bRow = (NT == 8) ? (t >> 1) : (t >> 2);
    const int bW   = (NT == 8) ? ((t & 1) * 8) : ((t & 3) * 4);
    const uint32_t* WphRow = Wph + (size_t)(n0 + bRow) * PK + koffp;
    const uint32_t* WplRow = Wpl + (size_t)(n0 + bRow) * PK + koffp;

    float acc[2][NT][4];
    #pragma unroll
    for (int mt = 0; mt < 2; mt++)
        #pragma unroll
        for (int nt = 0; nt < NT; nt++)
            #pragma unroll
            for (int q = 0; q < 4; q++) acc[mt][nt][q] = 0.f;

    const uint32_t smemBase = (uint32_t)__cvta_generic_to_shared(smem);
    const uint32_t aOfs = (uint32_t)(lrow * TSTR + lhw) * 4;
    const uint32_t bOfs = (uint32_t)(bRow * TSTR + bW) * 4;

    auto load_stage = [&](int s, int bf) {
        uint32_t stB = smemBase + (uint32_t)(bf * STAGE_W) * 4;
        const uint32_t* AH = (s < 16) ? AH0 : AH1;
        const uint32_t* AL = (s < 16) ? AL0 : AL1;
        const int pb = (s & 15) * 16;
        const uint32_t* ah = AH + (size_t)aRowC * PKA + pb + lhw;
        const uint32_t* al = AL + (size_t)aRowC * PKA + pb + lhw;
        cp_async16(stB + aOfs,                ah,     aOK);
        cp_async16(stB + aOfs + 16,           ah + 4, aOK);
        cp_async16(stB + A_SEG * 4 + aOfs,      al,     aOK);
        cp_async16(stB + A_SEG * 4 + aOfs + 16, al + 4, aOK);
        uint32_t bhB = stB + 2 * A_SEG * 4 + bOfs;
        uint32_t blB = bhB + B_SEG * 4;
        const uint32_t* bh = WphRow + s * 16 + bW;
        const uint32_t* bl = WplRow + s * 16 + bW;
        if (NT == 8) {
            cp_async16(bhB,      bh,     16);
            cp_async16(bhB + 16, bh + 4, 16);
            cp_async16(blB,      bl,     16);
            cp_async16(blB + 16, bl + 4, 16);
        } else {
            cp_async16(bhB, bh, 16);
            cp_async16(blB, bl, 16);
        }
    };

    load_stage(0, 0);
    cp_commit();

    for (int s = 0; s < nstages; s++) {
        const int bf = s & 1;
        if (s + 1 < nstages) { load_stage(s + 1, bf ^ 1); cp_commit(); cp_wait<1>(); }
        else                 { cp_wait<0>(); }
        __syncthreads();

        const uint32_t* AHb = smem + bf * STAGE_W;
        const uint32_t* ALb = AHb + A_SEG;
        const uint32_t* BHb = AHb + 2 * A_SEG;
        const uint32_t* BLb = BHb + B_SEG;

        #pragma unroll
        for (int w = 0; w < 2; w++) {
            uint32_t ah[2][4], al[2][4];
            #pragma unroll
            for (int mt = 0; mt < 2; mt++) {
                int r = warpM * 32 + mt * 16 + gid;
                int b0 = r * TSTR + w * 8 + tig;
                ah[mt][0] = AHb[b0];
                ah[mt][1] = AHb[b0 + 8 * TSTR];
                ah[mt][2] = AHb[b0 + 4];
                ah[mt][3] = AHb[b0 + 8 * TSTR + 4];
                al[mt][0] = ALb[b0];
                al[mt][1] = ALb[b0 + 8 * TSTR];
                al[mt][2] = ALb[b0 + 4];
                al[mt][3] = ALb[b0 + 8 * TSTR + 4];
            }
            #pragma unroll
            for (int nt = 0; nt < NT; nt++) {
                int n = warpN * (NT * 8) + nt * 8 + gid;
                int nb = n * TSTR + w * 8 + tig;
                uint32_t bh[2], bl[2];
                bh[0] = BHb[nb];
                bh[1] = BHb[nb + 4];
                bl[0] = BLb[nb];
                bl[1] = BLb[nb + 4];
                #pragma unroll
                for (int mt = 0; mt < 2; mt++) {
                    mma_bf16(acc[mt][nt], al[mt], bh);
                    mma_bf16(acc[mt][nt], ah[mt], bl);
                    mma_bf16(acc[mt][nt], ah[mt], bh);
                }
            }
        }
        __syncthreads();
    }

    #pragma unroll
    for (int nt = 0; nt < NT; nt++) {
        int cbase = n0 + warpN * (NT * 8) + nt * 8 + tig * 2;
        float b0 = biasp ? __ldg(&biasp[cbase])     : 0.f;
        float b1 = biasp ? __ldg(&biasp[cbase + 1]) : 0.f;
        #pragma unroll
        for (int mt = 0; mt < 2; mt++) {
            int r0 = m0 + warpM * 32 + mt * 16 + gid;
            int r1 = r0 + 8;
            float2 o0, o1;
            o0.x = acc[mt][nt][0] + b0; o0.y = acc[mt][nt][1] + b1;
            o1.x = acc[mt][nt][2] + b0; o1.y = acc[mt][nt][3] + b1;
            if (do_relu) {
                o0.x = fmaxf(o0.x, 0.f); o0.y = fmaxf(o0.y, 0.f);
                o1.x = fmaxf(o1.x, 0.f); o1.y = fmaxf(o1.y, 0.f);
            }
            if (OutH) {
                int p = cbase >> 1;
                uint32_t hi, lo;
                if (r0 < M) {
                    split2_bf16(o0.x, o0.y, hi, lo);
                    OutH[(size_t)r0 * PKA + p] = hi;
                    OutL[(size_t)r0 * PKA + p] = lo;
                }
                if (r1 < M) {
                    split2_bf16(o1.x, o1.y, hi, lo);
                    OutH[(size_t)r1 * PKA + p] = hi;
                    OutL[(size_t)r1 * PKA + p] = lo;
                }
            } else {
                if (r0 < M) *(float2*)(C + (size_t)r0 * N + cbase) = o0;
                if (r1 < M) *(float2*)(C + (size_t)r1 * N + cbase) = o1;
            }
        }
    }
}

// NT=4 variant: 128x64 tile, occ 3
__global__ __launch_bounds__(256, 3)
void gemm_nt4_kernel(const uint32_t* AH0, const uint32_t* AL0,
                     const uint32_t* AH1, const uint32_t* AL1,
                     const uint32_t* Wph, const uint32_t* Wpl,
                     const float* bias,
                     uint32_t* OutH, uint32_t* OutL,
                     int M, int N, int nstages) {
    gemm_body<4, false>(AH0, AL0, AH1, AL1, Wph, Wpl, bias,
                        nullptr, nullptr, OutH, OutL,
                        M, N, 1, nstages, 0, 0);
}

// NT=8 dual variant: 128x128 tile, occ 2
__global__ __launch_bounds__(256, 2)
void gemm_nt8_dual_kernel(const uint32_t* AH0, const uint32_t* AL0,
                          const uint32_t* Wph, const uint32_t* Wpl,
                          const float* bias,
                          float* C, float* Calt,
                          int M, int N, int nstages, int koffp, int koffpAlt) {
    gemm_body<8, true>(AH0, AL0, AH0, AL0, Wph, Wpl, bias,
                       C, Calt, nullptr, nullptr,
                       M, N, 0, nstages, koffp, koffpAlt);
}

#define NT4_SMEM_BYTES (2 * (2 * A_SEG + 2 * 64 * TSTR) * 4)    // 61440
#define NT8_SMEM_BYTES (2 * (2 * A_SEG + 2 * 128 * TSTR) * 4)   // 81920

// ---------------------------------------------------------------------------
// Launch.  Inputs: h, W1, b1, W2, b2, src, dst
// ---------------------------------------------------------------------------
extern "C" void kernel_launch(void* const* d_in, const int* in_sizes, int n_in,
                              void* d_out, int out_size) {
    const float* h   = (const float*)d_in[0];
    const float* W1  = (const float*)d_in[1];
    const float* b1  = (const float*)d_in[2];
    const float* W2  = (const float*)d_in[3];
    const float* b2  = (const float*)d_in[4];
    const int*   src = (const int*)d_in[5];
    const int*   dst = (const int*)d_in[6];
    float*       out = (float*)d_out;

    float *Y2, *P2;
    uint32_t *hPh, *hPl, *hNPh, *hNPl, *h1Ph, *h1Pl, *W1ph, *W1pl, *W2ph, *W2pl;
    cudaGetSymbolAddress((void**)&Y2,   g_Y2);
    cudaGetSymbolAddress((void**)&P2,   g_P2);
    cudaGetSymbolAddress((void**)&hPh,  g_hPh);
    cudaGetSymbolAddress((void**)&hPl,  g_hPl);
    cudaGetSymbolAddress((void**)&hNPh, g_hNPh);
    cudaGetSymbolAddress((void**)&hNPl, g_hNPl);
    cudaGetSymbolAddress((void**)&h1Ph, g_h1Ph);
    cudaGetSymbolAddress((void**)&h1Pl, g_h1Pl);
    cudaGetSymbolAddress((void**)&W1ph, g_W1ph);
    cudaGetSymbolAddress((void**)&W1pl, g_W1pl);
    cudaGetSymbolAddress((void**)&W2ph, g_W2ph);
    cudaGetSymbolAddress((void**)&W2pl, g_W2pl);

    cudaFuncSetAttribute(gemm_nt4_kernel,
                         cudaFuncAttributeMaxDynamicSharedMemorySize, NT4_SMEM_BYTES);
    cudaFuncSetAttribute(gemm_nt8_dual_kernel,
                         cudaFuncAttributeMaxDynamicSharedMemorySize, NT8_SMEM_BYTES);

    const int TB = 256;
    const int MT = (N_NODES + 127) / 128;  // 79

    // CSR build
    count_kernel<<<(N_EDGES + TB - 1) / TB, TB>>>(dst);
    scan_kernel<<<1, 1024>>>();
    fill_kernel<<<(N_EDGES + TB - 1) / TB, TB>>>(src, dst);

    // Weight packs
    pack_w_all_kernel<<<dim3(20, K_TOT / 64), dim3(32, 8)>>>(W1, W2);

    // agg(h)->packed + pack(h)
    agg512_pack2_kernel<<<N_NODES, 128>>>(h);

    // Layer 1: h1P = packed(relu([h, agg(h)] @ W1 + b1)), 128x64 tiles, occ 3
    {
        dim3 grid(H_FEATS / 64, MT);   // 8 x 79
        gemm_nt4_kernel<<<grid, 256, NT4_SMEM_BYTES>>>(
            hPh, hPl, hNPh, hNPl, W1ph, W1pl, b1,
            h1Ph, h1Pl, N_NODES, H_FEATS, 32);
    }

    // Layer 2 dual: x=0 -> Y2 = h1 @ W2[512:] (koffp=256); x=1 -> P2 = h1 @ W2[:512] + b2
    {
        dim3 grid(2, MT);
        gemm_nt8_dual_kernel<<<grid, 256, NT8_SMEM_BYTES>>>(
            h1Ph, h1Pl, W2ph, W2pl, b2,
            Y2, P2, N_NODES, N_CLASSES, 16, 256, 0);
    }

    // out = P2 + agg(Y2); re-zero cnt/cur
    agg128_final_kernel<<<(N_NODES + 3) / 4, 128>>>(Y2, P2, out);
}

// round 14
// speedup vs baseline: 1.7325x; 1.0694x over previous
#include <cuda_runtime.h>
#include <cuda_bf16.h>
#include <stdint.h>

#define N_NODES   10000
#define N_EDGES   160000
#define F_IN      512
#define H_FEATS   512
#define N_CLASSES 128
#define PKA       (F_IN / 2)     // 256 pairs per activation row
#define PKW2      512            // pairs per W2 row (K=1024)

// ---------------------------------------------------------------------------
// Device scratch (BSS zero-init; g_cnt/g_cur re-zeroed by tail kernel)
// ---------------------------------------------------------------------------
__device__ int   g_cnt[N_NODES];
__device__ int   g_cur[N_NODES];
__device__ int   g_off[N_NODES + 1];
__device__ int   g_adj[N_EDGES];
__device__ float g_U  [(size_t)N_NODES * H_FEATS];   // h @ W1_top
__device__ float g_V  [(size_t)N_NODES * H_FEATS];   // h @ W1_bot
__device__ float g_Y2 [(size_t)N_NODES * N_CLASSES];
__device__ float g_P2 [(size_t)N_NODES * N_CLASSES];
__device__ uint32_t g_hPh [(size_t)N_NODES * PKA];
__device__ uint32_t g_hPl [(size_t)N_NODES * PKA];
__device__ uint32_t g_h1Ph[(size_t)N_NODES * PKA];
__device__ uint32_t g_h1Pl[(size_t)N_NODES * PKA];
// W1 fused-B layout: B'[k, n'] (n'<512 -> W1[k,n']; n'>=512 -> W1[512+k, n'-512])
__device__ uint32_t g_W1ph[(size_t)1024 * PKA];      // [n'=1024][256 pairs]
__device__ uint32_t g_W1pl[(size_t)1024 * PKA];
__device__ uint32_t g_W2ph[(size_t)N_CLASSES * PKW2];
__device__ uint32_t g_W2pl[(size_t)N_CLASSES * PKW2];

// ---------------------------------------------------------------------------
// helpers
// ---------------------------------------------------------------------------
__device__ __forceinline__ void cp_async16(uint32_t dst, const void* src, int src_bytes) {
    asm volatile("cp.async.cg.shared.global [%0], [%1], 16, %2;"
                 :: "r"(dst), "l"(src), "r"(src_bytes));
}
__device__ __forceinline__ void cp_commit() {
    asm volatile("cp.async.commit_group;" ::: "memory");
}
template <int N>
__device__ __forceinline__ void cp_wait() {
    asm volatile("cp.async.wait_group %0;" :: "n"(N) : "memory");
}
__device__ __forceinline__ void mma_bf16(float* c, const uint32_t* a, const uint32_t* b) {
    asm volatile(
        "mma.sync.aligned.m16n8k16.row.col.f32.bf16.bf16.f32 "
        "{%0,%1,%2,%3}, {%4,%5,%6,%7}, {%8,%9}, {%0,%1,%2,%3};"
        : "+f"(c[0]), "+f"(c[1]), "+f"(c[2]), "+f"(c[3])
        : "r"(a[0]), "r"(a[1]), "r"(a[2]), "r"(a[3]), "r"(b[0]), "r"(b[1]));
}
__device__ __forceinline__ uint32_t pack_bf16x2(float x0, float x1) {
    uint32_t r;
    asm("cvt.rn.bf16x2.f32 %0, %1, %2;" : "=r"(r) : "f"(x1), "f"(x0));
    return r;
}
__device__ __forceinline__ void split2_bf16(float x0, float x1, uint32_t& hi, uint32_t& lo) {
    hi = pack_bf16x2(x0, x1);
    float h0 = __uint_as_float(hi << 16);
    float h1 = __uint_as_float(hi & 0xFFFF0000u);
    lo = pack_bf16x2(x0 - h0, x1 - h1);
}

// ---------------------------------------------------------------------------
// CSR build
// ---------------------------------------------------------------------------
__global__ void count_kernel(const int* __restrict__ dst) {
    int e = blockIdx.x * blockDim.x + threadIdx.x;
    if (e < N_EDGES) atomicAdd(&g_cnt[dst[e]], 1);
}
__global__ void scan_kernel() {
    __shared__ int wsum[32];
    __shared__ int chunk_total;
    const int lane = threadIdx.x & 31;
    const int wid  = threadIdx.x >> 5;
    int running = 0;
    for (int base = 0; base < N_NODES; base += 1024) {
        int i = base + threadIdx.x;
        int v = (i < N_NODES) ? g_cnt[i] : 0;
        int s = v;
        #pragma unroll
        for (int o = 1; o < 32; o <<= 1) {
            int u = __shfl_up_sync(0xffffffffu, s, o);
            if (lane >= o) s += u;
        }
        if (lane == 31) wsum[wid] = s;
        __syncthreads();
        if (wid == 0) {
            int ws = wsum[lane];
            #pragma unroll
            for (int o = 1; o < 32; o <<= 1) {
                int u = __shfl_up_sync(0xffffffffu, ws, o);
                if (lane >= o) ws += u;
            }
            wsum[lane] = ws;
            if (lane == 31) chunk_total = ws;
        }
        __syncthreads();
        int wpref = (wid > 0) ? wsum[wid - 1] : 0;
        if (i < N_NODES) g_off[i] = running + wpref + s - v;
        running += chunk_total;
        __syncthreads();
    }
    if (threadIdx.x == 0) g_off[N_NODES] = running;
}
__global__ void fill_kernel(const int* __restrict__ src, const int* __restrict__ dst) {
    int e = blockIdx.x * blockDim.x + threadIdx.x;
    if (e < N_EDGES) {
        int d = dst[e];
        int p = atomicAdd(&g_cur[d], 1);
        g_adj[g_off[d] + p] = src[e];
    }
}

// ---------------------------------------------------------------------------
// pack_all: W1 (fused-B layout), W2, and h, one launch.
// grid (76, 16), block (32, 8):
//   bx <  32 : W1  (n0 = bx*32, k0 = by*64, by<8 only)
//   32<=bx<36: W2  (n0 = (bx-32)*32, k0 = by*64)
//   bx >= 36 : h   chunk = (bx-36)*16 + by, 4000 pairs each
// ---------------------------------------------------------------------------
__global__ void pack_all_kernel(const float* __restrict__ W1,
                                const float* __restrict__ W2,
                                const float* __restrict__ h) {
    __shared__ float sh[64][33];
    const int tx = threadIdx.x, ty = threadIdx.y;
    const int tid = ty * 32 + tx;

    if (blockIdx.x >= 36) {
        int chunk = (blockIdx.x - 36) * 16 + blockIdx.y;
        int base = chunk * 4000;
        const float2* h2 = (const float2*)h;
        for (int i = tid; i < 4000; i += 256) {
            int p = base + i;
            float2 v = h2[p];
            uint32_t hi, lo;
            split2_bf16(v.x, v.y, hi, lo);
            g_hPh[p] = hi;
            g_hPl[p] = lo;
        }
        return;
    }

    const bool isW1 = (blockIdx.x < 32);
    if (isW1 && blockIdx.y >= 8) return;

    const float* W;
    uint32_t *Wph, *Wpl;
    int srcRow0, srcCol0, srcLd, n0, ldP;
    int k0 = blockIdx.y * 64;
    if (isW1) {
        n0 = blockIdx.x * 32;
        srcRow0 = k0 + (n0 >= 512 ? 512 : 0);
        srcCol0 = n0 & 511;
        srcLd = 512;
        W = W1; Wph = g_W1ph; Wpl = g_W1pl; ldP = PKA;
    } else {
        n0 = (blockIdx.x - 32) * 32;
        srcRow0 = k0;
        srcCol0 = n0;
        srcLd = 128;
        W = W2; Wph = g_W2ph; Wpl = g_W2pl; ldP = PKW2;
    }

    #pragma unroll
    for (int j = 0; j < 64; j += 8)
        sh[j + ty][tx] = W[(size_t)(srcRow0 + j + ty) * srcLd + srcCol0 + tx];
    __syncthreads();
    #pragma unroll
    for (int j = 0; j < 32; j += 8) {
        int nl = ty + j;
        float x0 = sh[2 * tx][nl];
        float x1 = sh[2 * tx + 1][nl];
        uint32_t hi, lo;
        split2_bf16(x0, x1, hi, lo);
        size_t o = (size_t)(n0 + nl) * ldP + (k0 >> 1) + tx;
        Wph[o] = hi;
        Wpl[o] = lo;
    }
}

// ---------------------------------------------------------------------------
// Fused layer-1 tail: h1 = relu(U[n] + mean_{s in N(n)} V[s] + b1), packed out.
// ---------------------------------------------------------------------------
__global__ void agg_relu_pack_kernel(const float* __restrict__ b1) {
    int n   = blockIdx.x;
    int st  = g_off[n];
    int deg = g_off[n + 1] - st;
    int c4  = threadIdx.x;

    float4 acc = make_float4(0.f, 0.f, 0.f, 0.f);
    int e = 0;
    for (; e + 1 < deg; e += 2) {
        int s0 = g_adj[st + e];
        int s1 = g_adj[st + e + 1];
        float4 v0 = *(const float4*)(g_V + (size_t)s0 * 512 + c4 * 4);
        float4 v1 = *(const float4*)(g_V + (size_t)s1 * 512 + c4 * 4);
        acc.x += v0.x + v1.x; acc.y += v0.y + v1.y;
        acc.z += v0.z + v1.z; acc.w += v0.w + v1.w;
    }
    if (e < deg) {
        int s0 = g_adj[st + e];
        float4 v0 = *(const float4*)(g_V + (size_t)s0 * 512 + c4 * 4);
        acc.x += v0.x; acc.y += v0.y; acc.z += v0.z; acc.w += v0.w;
    }
    float inv = (deg > 0) ? (1.0f / (float)deg) : 0.0f;
    float4 u = *(const float4*)(g_U + (size_t)n * 512 + c4 * 4);
    float4 b = *(const float4*)(b1 + c4 * 4);
    float v0 = fmaxf(u.x + acc.x * inv + b.x, 0.f);
    float v1 = fmaxf(u.y + acc.y * inv + b.y, 0.f);
    float v2 = fmaxf(u.z + acc.z * inv + b.z, 0.f);
    float v3 = fmaxf(u.w + acc.w * inv + b.w, 0.f);
    uint32_t h0, l0, h1, l1;
    split2_bf16(v0, v1, h0, l0);
    split2_bf16(v2, v3, h1, l1);
    ((uint2*)(g_h1Ph + (size_t)n * PKA))[c4] = make_uint2(h0, h1);
    ((uint2*)(g_h1Pl + (size_t)n * PKA))[c4] = make_uint2(l0, l1);
}

// out[n] = P2[n] + mean Y2[neigh]; re-zero cnt/cur for next call
__global__ void agg128_final_kernel(float* __restrict__ out) {
    int gi = blockIdx.x * blockDim.x + threadIdx.x;
    if (gi < N_NODES) { g_cnt[gi] = 0; g_cur[gi] = 0; }

    int n = blockIdx.x * 4 + (threadIdx.x >> 5);
    int lane = threadIdx.x & 31;
    if (n >= N_NODES) return;
    int st  = g_off[n];
    int deg = g_off[n + 1] - st;
    float4 acc = make_float4(0.f, 0.f, 0.f, 0.f);
    int e = 0;
    for (; e + 1 < deg; e += 2) {
        int s0 = g_adj[st + e];
        int s1 = g_adj[st + e + 1];
        float4 v0 = *(const float4*)(g_Y2 + (size_t)s0 * 128 + lane * 4);
        float4 v1 = *(const float4*)(g_Y2 + (size_t)s1 * 128 + lane * 4);
        acc.x += v0.x + v1.x; acc.y += v0.y + v1.y;
        acc.z += v0.z + v1.z; acc.w += v0.w + v1.w;
    }
    if (e < deg) {
        int s0 = g_adj[st + e];
        float4 v0 = *(const float4*)(g_Y2 + (size_t)s0 * 128 + lane * 4);
        acc.x += v0.x; acc.y += v0.y; acc.z += v0.z; acc.w += v0.w;
    }
    float inv = (deg > 0) ? (1.0f / (float)deg) : 0.0f;
    float4 p = *(const float4*)(g_P2 + (size_t)n * 128 + lane * 4);
    acc.x = acc.x * inv + p.x; acc.y = acc.y * inv + p.y;
    acc.z = acc.z * inv + p.z; acc.w = acc.w * inv + p.w;
    *(float4*)(out + (size_t)n * 128 + lane * 4) = acc;
}

// ---------------------------------------------------------------------------
// bf16x3 GEMM, K=512 (16 stages of BK=32), all operands pre-packed.
// MODE 0 (NT=4): split-UV output. n' in [0,1024); cols <512 -> U, else V. f32.
// MODE 1 (NT=8): dual output. bx=0 -> Y2 (koffp0), bx=1 -> P2+bias (koffp1).
// ---------------------------------------------------------------------------
#define TSTR 20
#define A_SEG (128 * TSTR)
#define NSTAGES 16

template <int NT, int MODE>
__device__ __forceinline__ void gemm_body(
        const uint32_t* __restrict__ AH, const uint32_t* __restrict__ AL,
        const uint32_t* __restrict__ Wph, const uint32_t* __restrict__ Wpl, int ldP,
        const float* __restrict__ bias,
        float* __restrict__ D0, float* __restrict__ D1,
        int M, int koffp0, int koffp1) {
    extern __shared__ uint32_t smem[];

    constexpr int BN    = 16 * NT;
    constexpr int B_SEG = BN * TSTR;
    constexpr int STAGE_W = 2 * A_SEG + 2 * B_SEG;

    const int t     = threadIdx.x;
    const int lane  = t & 31;
    const int wid   = t >> 5;
    const int warpM = wid & 3;
    const int warpN = wid >> 2;
    const int gid   = lane >> 2;
    const int tig   = lane & 3;
    const int m0    = blockIdx.y * 128;

    int n0, koffp;
    float* D = D0;
    const float* biasp = nullptr;
    if (MODE == 0) {
        n0 = blockIdx.x * BN;
        koffp = koffp0;
    } else {
        n0 = 0;
        if (blockIdx.x == 0) { D = D0; koffp = koffp0; }
        else                 { D = D1; koffp = koffp1; biasp = bias; }
    }

    const int lrow  = t >> 1;
    const int lhw   = (t & 1) * 8;
    const int aRow  = m0 + lrow;
    const int aOK   = (aRow < M) ? 16 : 0;
    const int aRowC = (aRow < M) ? aRow : 0;
    const int bRow = (NT == 8) ? (t >> 1) : (t >> 2);
    const int bW   = (NT == 8) ? ((t & 1) * 8) : ((t & 3) * 4);
    const uint32_t* WphRow = Wph + (size_t)(n0 + bRow) * ldP + koffp;
    const uint32_t* WplRow = Wpl + (size_t)(n0 + bRow) * ldP + koffp;

    float acc[2][NT][4];
    #pragma unroll
    for (int mt = 0; mt < 2; mt++)
        #pragma unroll
        for (int nt = 0; nt < NT; nt++)
            #pragma unroll
            for (int q = 0; q < 4; q++) acc[mt][nt][q] = 0.f;

    const uint32_t smemBase = (uint32_t)__cvta_generic_to_shared(smem);
    const uint32_t aOfs = (uint32_t)(lrow * TSTR + lhw) * 4;
    const uint32_t bOfs = (uint32_t)(bRow * TSTR + bW) * 4;

    auto load_stage = [&](int s, int bf) {
        uint32_t stB = smemBase + (uint32_t)(bf * STAGE_W) * 4;
        const int pb = s * 16;
        const uint32_t* ah = AH + (size_t)aRowC * PKA + pb + lhw;
        const uint32_t* al = AL + (size_t)aRowC * PKA + pb + lhw;
        cp_async16(stB + aOfs,                  ah,     aOK);
        cp_async16(stB + aOfs + 16,             ah + 4, aOK);
        cp_async16(stB + A_SEG * 4 + aOfs,      al,     aOK);
        cp_async16(stB + A_SEG * 4 + aOfs + 16, al + 4, aOK);
        uint32_t bhB = stB + 2 * A_SEG * 4 + bOfs;
        uint32_t blB = bhB + B_SEG * 4;
        const uint32_t* bh = WphRow + pb + bW;
        const uint32_t* bl = WplRow + pb + bW;
        if (NT == 8) {
            cp_async16(bhB,      bh,     16);
            cp_async16(bhB + 16, bh + 4, 16);
            cp_async16(blB,      bl,     16);
            cp_async16(blB + 16, bl + 4, 16);
        } else {
            cp_async16(bhB, bh, 16);
            cp_async16(blB, bl, 16);
        }
    };

    load_stage(0, 0);
    cp_commit();

    for (int s = 0; s < NSTAGES; s++) {
        const int bf = s & 1;
        if (s + 1 < NSTAGES) { load_stage(s + 1, bf ^ 1); cp_commit(); cp_wait<1>(); }
        else                 { cp_wait<0>(); }
        __syncthreads();

        const uint32_t* AHb = smem + bf * STAGE_W;
        const uint32_t* ALb = AHb + A_SEG;
        const uint32_t* BHb = AHb + 2 * A_SEG;
        const uint32_t* BLb = BHb + B_SEG;

        #pragma unroll
        for (int w = 0; w < 2; w++) {
            uint32_t ah[2][4], al[2][4];
            #pragma unroll
            for (int mt = 0; mt < 2; mt++) {
                int r = warpM * 32 + mt * 16 + gid;
                int b0 = r * TSTR + w * 8 + tig;
                ah[mt][0] = AHb[b0];
                ah[mt][1] = AHb[b0 + 8 * TSTR];
                ah[mt][2] = AHb[b0 + 4];
                ah[mt][3] = AHb[b0 + 8 * TSTR + 4];
                al[mt][0] = ALb[b0];
                al[mt][1] = ALb[b0 + 8 * TSTR];
                al[mt][2] = ALb[b0 + 4];
                al[mt][3] = ALb[b0 + 8 * TSTR + 4];
            }
            #pragma unroll
            for (int nt = 0; nt < NT; nt++) {
                int n = warpN * (NT * 8) + nt * 8 + gid;
                int nb = n * TSTR + w * 8 + tig;
                uint32_t bh[2], bl[2];
                bh[0] = BHb[nb];
                bh[1] = BHb[nb + 4];
                bl[0] = BLb[nb];
                bl[1] = BLb[nb + 4];
                #pragma unroll
                for (int mt = 0; mt < 2; mt++) {
                    mma_bf16(acc[mt][nt], al[mt], bh);
                    mma_bf16(acc[mt][nt], ah[mt], bl);
                    mma_bf16(acc[mt][nt], ah[mt], bh);
                }
            }
        }
        __syncthreads();
    }

    #pragma unroll
    for (int nt = 0; nt < NT; nt++) {
        int cbase = n0 + warpN * (NT * 8) + nt * 8 + tig * 2;
        float b0 = biasp ? __ldg(&biasp[cbase])     : 0.f;
        float b1 = biasp ? __ldg(&biasp[cbase + 1]) : 0.f;
        #pragma unroll
        for (int mt = 0; mt < 2; mt++) {
            int r0 = m0 + warpM * 32 + mt * 16 + gid;
            int r1 = r0 + 8;
            float2 o0, o1;
            o0.x = acc[mt][nt][0] + b0; o0.y = acc[mt][nt][1] + b1;
            o1.x = acc[mt][nt][2] + b0; o1.y = acc[mt][nt][3] + b1;
            if (MODE == 0) {
                float* dst = (cbase < 512) ? D0 : D1;
                int cc = cbase & 511;
                if (r0 < M) *(float2*)(dst + (size_t)r0 * 512 + cc) = o0;
                if (r1 < M) *(float2*)(dst + (size_t)r1 * 512 + cc) = o1;
            } else {
                if (r0 < M) *(float2*)(D + (size_t)r0 * 128 + cbase) = o0;
                if (r1 < M) *(float2*)(D + (size_t)r1 * 128 + cbase) = o1;
            }
        }
    }
}

// GEMM1: split UV, NT=4, occ 3
__global__ __launch_bounds__(256, 3)
void gemm1_kernel(const uint32_t* AH, const uint32_t* AL,
                  const uint32_t* Wph, const uint32_t* Wpl,
                  float* U, float* V, int M) {
    gemm_body<4, 0>(AH, AL, Wph, Wpl, PKA, nullptr, U, V, M, 0, 0);
}

// GEMM2: dual, NT=8, occ 2
__global__ __launch_bounds__(256, 2)
void gemm2_kernel(const uint32_t* AH, const uint32_t* AL,
                  const uint32_t* Wph, const uint32_t* Wpl,
                  const float* bias, float* Y2, float* P2, int M) {
    gemm_body<8, 1>(AH, AL, Wph, Wpl, PKW2, bias, Y2, P2, M, 256, 0);
}

#define NT4_SMEM_BYTES (2 * (2 * A_SEG + 2 * 64 * TSTR) * 4)    // 61440
#define NT8_SMEM_BYTES (2 * (2 * A_SEG + 2 * 128 * TSTR) * 4)   // 81920

// ---------------------------------------------------------------------------
// Launch.  Inputs: h, W1, b1, W2, b2, src, dst
// h1 = relu(h@W1_top + agg(h@W1_bot) + b1)
// out = h1@W2_top + b2 + agg(h1@W2_bot)
// ---------------------------------------------------------------------------
extern "C" void kernel_launch(void* const* d_in, const int* in_sizes, int n_in,
                              void* d_out, int out_size) {
    const float* h   = (const float*)d_in[0];
    const float* W1  = (const float*)d_in[1];
    const float* b1  = (const float*)d_in[2];
    const float* W2  = (const float*)d_in[3];
    const float* b2  = (const float*)d_in[4];
    const int*   src = (const int*)d_in[5];
    const int*   dst = (const int*)d_in[6];
    float*       out = (float*)d_out;

    float *U, *V, *Y2, *P2;
    uint32_t *hPh, *hPl, *h1Ph, *h1Pl, *W1ph, *W1pl, *W2ph, *W2pl;
    cudaGetSymbolAddress((void**)&U,    g_U);
    cudaGetSymbolAddress((void**)&V,    g_V);
    cudaGetSymbolAddress((void**)&Y2,   g_Y2);
    cudaGetSymbolAddress((void**)&P2,   g_P2);
    cudaGetSymbolAddress((void**)&hPh,  g_hPh);
    cudaGetSymbolAddress((void**)&hPl,  g_hPl);
    cudaGetSymbolAddress((void**)&h1Ph, g_h1Ph);
    cudaGetSymbolAddress((void**)&h1Pl, g_h1Pl);
    cudaGetSymbolAddress((void**)&W1ph, g_W1ph);
    cudaGetSymbolAddress((void**)&W1pl, g_W1pl);
    cudaGetSymbolAddress((void**)&W2ph, g_W2ph);
    cudaGetSymbolAddress((void**)&W2pl, g_W2pl);

    cudaFuncSetAttribute(gemm1_kernel,
                         cudaFuncAttributeMaxDynamicSharedMemorySize, NT4_SMEM_BYTES);
    cudaFuncSetAttribute(gemm2_kernel,
                         cudaFuncAttributeMaxDynamicSharedMemorySize, NT8_SMEM_BYTES);

    const int TB = 256;
    const int MT = (N_NODES + 127) / 128;  // 79

    // 1: pack W1 (fused-B layout), W2, h
    pack_all_kernel<<<dim3(76, 16), dim3(32, 8)>>>(W1, W2, h);

    // 2-3: CSR count + scan
    count_kernel<<<(N_EDGES + TB - 1) / TB, TB>>>(dst);
    scan_kernel<<<1, 1024>>>();

    // 4: GEMM1 -> U | V   (profiled launch)
    {
        dim3 grid(1024 / 64, MT);   // 16 x 79
        gemm1_kernel<<<grid, 256, NT4_SMEM_BYTES>>>(hPh, hPl, W1ph, W1pl, U, V, N_NODES);
    }

    // 5: CSR fill
    fill_kernel<<<(N_EDGES + TB - 1) / TB, TB>>>(src, dst);

    // 6: h1 = relu(U + agg(V) + b1), packed
    agg_relu_pack_kernel<<<N_NODES, 128>>>(b1);

    // 7: dual GEMM2: Y2 = h1@W2_bot, P2 = h1@W2_top + b2
    {
        dim3 grid(2, MT);
        gemm2_kernel<<<grid, 256, NT8_SMEM_BYTES>>>(h1Ph, h1Pl, W2ph, W2pl, b2, Y2, P2, N_NODES);
    }

    // 8: out = P2 + agg(Y2); re-zero cnt/cur
    agg128_final_kernel<<<(N_NODES + 3) / 4, 128>>>(out);
}